// round 14
// baseline (speedup 1.0000x reference)
#include <cuda_runtime.h>
#include <cstdint>

// ---------------- problem constants ----------------
#define NB   16
#define NC   256
#define HW   1024
#define DIM  1024

// ---------------- scratch (device globals; no allocation) ----------------
__device__ float g_x[NB * NC * HW];            // cdc output, then LN'd (tf32-rounded)
__device__ float g_vspa[NB * NC * HW];
__device__ float g_vfreq[NB * NC * HW];
__device__ float g_qk[NB * NC * 2 * HW];       // [b, c, 2048]: only cols 1024.. (k) written
__device__ float g_qT[NB * HW * NC];           // [b, n, c] written by qk GEMM epilogue
__device__ float g_kw[NB * NC * 2 * HW];       // [b, c, 2048]: kw_spa | kw_freq (rounded)
__device__ float g_E[NB * HW * 2 * HW];        // [b, n, 2048]: exp(logits), rounded
__device__ float g_part[NB * 2 * HW * 16];     // deterministic row-sum partials
__device__ float g_inv[NB * 2 * HW];           // 1/rowsum  [b][branch][n]
__device__ float g_bcat[2 * HW];               // b_spa | b_frq
__device__ float g_wqkT[DIM * 2 * DIM];
__device__ float g_wspaT[DIM * DIM];
__device__ float g_wfrqT[DIM * DIM];
__device__ float g_xspar[NB * NC * HW];        // rounded x copies; later reused as v*inv
__device__ float g_xfreqr[NB * NC * HW];
__device__ float g_wcdcr[NC * 2 * NC];
__device__ float g_wsvr[NC * NC];
__device__ float g_wfvr[NC * NC];

// ---------------- helpers ----------------
__device__ __forceinline__ float tf32r(float x) {
    asm("cvt.rna.tf32.f32 %0, %1;" : "=f"(x) : "f"(x));
    return x;
}
__device__ __forceinline__ void cpasync16(uint32_t dst, const void* src) {
    asm volatile("cp.async.cg.shared.global [%0], [%1], 16;\n" :: "r"(dst), "l"(src));
}
__device__ __forceinline__ void cpcommit() {
    asm volatile("cp.async.commit_group;\n");
}
__device__ __forceinline__ void cpwait1() {
    asm volatile("cp.async.wait_group 1;\n");
}
__device__ __forceinline__ void cpwait0() {
    asm volatile("cp.async.wait_group 0;\n");
}
__device__ __forceinline__ void mma_tf32(float* d, const uint32_t* a, const uint32_t* b) {
    asm volatile(
        "mma.sync.aligned.m16n8k8.row.col.f32.tf32.tf32.f32 "
        "{%0,%1,%2,%3}, {%4,%5,%6,%7}, {%8,%9}, {%0,%1,%2,%3};\n"
        : "+f"(d[0]), "+f"(d[1]), "+f"(d[2]), "+f"(d[3])
        : "r"(a[0]), "r"(a[1]), "r"(a[2]), "r"(a[3]), "r"(b[0]), "r"(b[1]));
}

// ---------------- tf32 tensor-core GEMM ----------------
// C[m,n] = alpha*sum_k A[m,k]*B[k,n] + biasRow[m] + biasCol[n] + Add[m,n]
// Operands MUST be tf32-pre-rounded. M%128==0, N%128==0, K%32==0.
// B2/kSplit: B rows k >= kSplit come from B2 (row k-kSplit); kSplit stage-aligned.
// partials != nullptr: exp epilogue (softmax numerator + deterministic row partials).
// qT != nullptr: qk-mode. bn<1024 tiles write ONLY transposed+rounded into
//   qT[b][n][c] (alpha/bias/Add ignored there); bn>=1024 tiles write C normally.
#define BM 128
#define BN 128
#define BKT 32
#define AS_LD 36
#define BS_LD 136
#define AS_FLOATS (BM * AS_LD)            // 4608
#define BS_FLOATS (BKT * BS_LD)           // 4352
#define STAGE_FLOATS (AS_FLOATS + BS_FLOATS)   // 8960
#define STAGE_BYTES (STAGE_FLOATS * 4)         // 35840
#define NSTAGES 2
#define SMEM_BYTES (STAGE_BYTES * NSTAGES)     // 71680 -> 3 CTAs/SM (215KB)

__global__ __launch_bounds__(128, 3)
void sgemm_tc(const float* __restrict__ A, int lda, long long sA,
              const float* __restrict__ B, int ldb, long long sB,
              const float* __restrict__ B2, int kSplit,
              const float* __restrict__ Add, long long sAdd,
              const float* __restrict__ biasRow, const float* __restrict__ biasCol,
              float* __restrict__ C, int ldc, long long sC,
              int K, float alpha, int roundC,
              float* __restrict__ partials, float* __restrict__ qT)
{
    extern __shared__ float smem[];
    const uint32_t smem_u32 = (uint32_t)__cvta_generic_to_shared(smem);

    const long long bz = blockIdx.z;
    A += bz * sA;
    B += bz * sB;
    if (B2) B2 += bz * sB;
    C += bz * sC;
    if (Add) Add += bz * sAdd;

    const int bm = blockIdx.y * BM;
    const int bn = blockIdx.x * BN;
    const int tid  = threadIdx.x;
    const int lane = tid & 31;
    const int wid  = tid >> 5;
    const int wm = wid >> 1;     // 0..1
    const int wn = wid & 1;      // 0..1
    const int rb = wm * 64;
    const int cb = wn * 64;
    const int lr = lane >> 2;    // 0..7
    const int lc = lane & 3;     // 0..3

    float acc[4][8][4];
#pragma unroll
    for (int i = 0; i < 4; i++)
#pragma unroll
        for (int j = 0; j < 8; j++)
#pragma unroll
            for (int v = 0; v < 4; v++) acc[i][j][v] = 0.f;

    const int a_row = tid >> 3;           // 0..15 (plus +16*u)
    const int a_k4  = (tid & 7) * 4;
    const int b_row = tid >> 5;           // 0..3 (plus +4*u)
    const int b_n4  = (tid & 31) * 4;

    const int T = K / BKT;

    auto load_stage = [&](int t, int s) {
        const int k0 = t * BKT;
        const uint32_t sa = smem_u32 + s * STAGE_BYTES;
        const uint32_t sb = sa + AS_FLOATS * 4;
#pragma unroll
        for (int u = 0; u < 8; u++) {
            const int r = a_row + u * 16;
            cpasync16(sa + (r * AS_LD + a_k4) * 4,
                      A + (long long)(bm + r) * lda + k0 + a_k4);
        }
        const float* Bb = B;
        int kk0 = k0;
        if (B2 && k0 >= kSplit) { Bb = B2; kk0 = k0 - kSplit; }
#pragma unroll
        for (int u = 0; u < 8; u++) {
            const int r = b_row + u * 4;
            cpasync16(sb + (r * BS_LD + b_n4) * 4,
                      Bb + (long long)(kk0 + r) * ldb + bn + b_n4);
        }
    };

    load_stage(0, 0); cpcommit();

    for (int t = 0; t < T; t++) {
        if (t + 1 < T) {
            load_stage(t + 1, (t + 1) & 1);
            cpcommit();
            cpwait1();
        } else {
            cpwait0();
        }
        __syncthreads();

        const float* sA_ = smem + (t & 1) * STAGE_FLOATS;
        const float* sB_ = sA_ + AS_FLOATS;

#pragma unroll
        for (int kk = 0; kk < 4; kk++) {
            const int kb = kk * 8 + lc;
            uint32_t a[4][4];
#pragma unroll
            for (int mi = 0; mi < 4; mi++) {
                const int m0 = rb + mi * 16 + lr;
                a[mi][0] = __float_as_uint(sA_[m0 * AS_LD + kb]);
                a[mi][1] = __float_as_uint(sA_[(m0 + 8) * AS_LD + kb]);
                a[mi][2] = __float_as_uint(sA_[m0 * AS_LD + kb + 4]);
                a[mi][3] = __float_as_uint(sA_[(m0 + 8) * AS_LD + kb + 4]);
            }
            uint32_t b[8][2];
#pragma unroll
            for (int ni = 0; ni < 8; ni++) {
                const int n0 = cb + ni * 8 + lr;
                b[ni][0] = __float_as_uint(sB_[kb * BS_LD + n0]);
                b[ni][1] = __float_as_uint(sB_[(kb + 4) * BS_LD + n0]);
            }
#pragma unroll
            for (int mi = 0; mi < 4; mi++)
#pragma unroll
                for (int ni = 0; ni < 8; ni++)
                    mma_tf32(acc[mi][ni], a[mi], b[ni]);
        }
        __syncthreads();
    }

    if (qT && bn < 1024) {
        // ---- qk-mode, q half: stage C tile to smem, write transposed+rounded qT
        float* s = smem;   // mainloop fully drained (final syncthreads above)
#pragma unroll
        for (int mi = 0; mi < 4; mi++) {
#pragma unroll
            for (int half = 0; half < 2; half++) {
                const int rl = rb + mi * 16 + lr + half * 8;
#pragma unroll
                for (int ni = 0; ni < 8; ni++) {
                    const int cl = cb + ni * 8 + lc * 2;
                    s[rl * 129 + cl]     = tf32r(acc[mi][ni][half * 2 + 0]);
                    s[rl * 129 + cl + 1] = tf32r(acc[mi][ni][half * 2 + 1]);
                }
            }
        }
        __syncthreads();
        float* qTb = qT + bz * (long long)(HW * NC);
        for (int i = 0; i < 32; i++) {
            const int nl = wid * 32 + i;
            float* row = qTb + (long long)(bn + nl) * 256 + bm;
#pragma unroll
            for (int u = 0; u < 4; u++)
                row[lane + 32 * u] = s[(lane + 32 * u) * 129 + nl];
        }
        return;
    }

    if (partials) {
        // ---- exp epilogue: E = tf32r(exp(clamp(alpha*acc + biasCol))) + row partials
        const int h = bn >> 10;                       // branch
        const int slot = ((bn & 1023) + cb) >> 6;     // 0..15
#pragma unroll
        for (int mi = 0; mi < 4; mi++) {
#pragma unroll
            for (int half = 0; half < 2; half++) {
                const int r = bm + rb + mi * 16 + lr + half * 8;
                const long long rowoff = (long long)r * ldc;
                float rowsum = 0.f;
#pragma unroll
                for (int ni = 0; ni < 8; ni++) {
                    const int c = bn + cb + ni * 8 + lc * 2;
                    const float2 bc = *(const float2*)(biasCol + c);
                    float f0 = alpha * acc[mi][ni][half * 2 + 0] + bc.x;
                    float f1 = alpha * acc[mi][ni][half * 2 + 1] + bc.y;
                    f0 = fminf(fmaxf(f0, -80.f), 80.f);
                    f1 = fminf(fmaxf(f1, -80.f), 80.f);
                    f0 = tf32r(__expf(f0));
                    f1 = tf32r(__expf(f1));
                    rowsum += f0 + f1;
                    float2 o; o.x = f0; o.y = f1;
                    *(float2*)(C + rowoff + c) = o;
                }
                rowsum += __shfl_xor_sync(0xffffffffu, rowsum, 1);
                rowsum += __shfl_xor_sync(0xffffffffu, rowsum, 2);
                if (lc == 0) {
                    const long long pidx =
                        (((long long)bz * 2048 + h * 1024 + r) << 4) + slot;
                    partials[pidx] = rowsum;
                }
            }
        }
    } else {
#pragma unroll
        for (int mi = 0; mi < 4; mi++) {
#pragma unroll
            for (int half = 0; half < 2; half++) {
                const int r = bm + rb + mi * 16 + lr + half * 8;
                const float br = biasRow ? biasRow[r] : 0.f;
                const long long rowoff = (long long)r * ldc;
#pragma unroll
                for (int ni = 0; ni < 8; ni++) {
                    const int c = bn + cb + ni * 8 + lc * 2;
                    float f0 = alpha * acc[mi][ni][half * 2 + 0] + br;
                    float f1 = alpha * acc[mi][ni][half * 2 + 1] + br;
                    if (biasCol) {
                        const float2 bc = *(const float2*)(biasCol + c);
                        f0 += bc.x; f1 += bc.y;
                    }
                    if (Add) {
                        const float2 ad = *(const float2*)(Add + rowoff + c);
                        f0 += ad.x; f1 += ad.y;
                    }
                    if (roundC) { f0 = tf32r(f0); f1 = tf32r(f1); }
                    float2 o; o.x = f0; o.y = f1;
                    *(float2*)(C + rowoff + c) = o;
                }
            }
        }
    }
}

// ---------------- tf32 rounding pass ----------------
__global__ __launch_bounds__(256)
void round_k(const float4* __restrict__ in, float4* __restrict__ out, int n4)
{
    int i = blockIdx.x * 256 + threadIdx.x;
    if (i < n4) {
        float4 v = in[i];
        v.x = tf32r(v.x); v.y = tf32r(v.y); v.z = tf32r(v.z); v.w = tf32r(v.w);
        out[i] = v;
    }
}

// ---------------- v' = tf32r(v * inv[n])  (columns scaled) ----------------
// v: [b, c, 1024]; inv: per-branch base, batch stride 2048 floats.
__global__ __launch_bounds__(256)
void vscale_k(const float4* __restrict__ v, const float* __restrict__ inv,
              float4* __restrict__ out)
{
    const long long i = (long long)blockIdx.x * 256 + threadIdx.x;  // < NB*NC*HW/4
    const int b  = (int)(i >> 16);          // NC*HW/4 = 65536 float4 per batch
    const int n4 = (int)(i & 255);          // HW/4
    float4 vv = v[i];
    const float4 iv = *(const float4*)(inv + (long long)b * 2048 + n4 * 4);
    vv.x = tf32r(vv.x * iv.x);
    vv.y = tf32r(vv.y * iv.y);
    vv.z = tf32r(vv.z * iv.z);
    vv.w = tf32r(vv.w * iv.w);
    out[i] = vv;
}

// ---------------- reduce partials -> inverse row sums ----------------
__global__ __launch_bounds__(256)
void inv_k(const float* __restrict__ part, float* __restrict__ inv, int n)
{
    int i = blockIdx.x * 256 + threadIdx.x;
    if (i < n) {
        const float4* p = (const float4*)(part + ((long long)i << 4));
        float4 a = p[0], b = p[1], c = p[2], d = p[3];
        float s = ((a.x + a.y) + (a.z + a.w)) + ((b.x + b.y) + (b.z + b.w))
                + ((c.x + c.y) + (c.z + c.w)) + ((d.x + d.y) + (d.z + d.w));
        inv[i] = 1.f / s;
    }
}

// ---------------- concat biases ----------------
__global__ __launch_bounds__(256)
void bcat_k(const float* __restrict__ b0, const float* __restrict__ b1,
            float* __restrict__ out)
{
    int i = blockIdx.x * 256 + threadIdx.x;
    if (i < 2048) out[i] = (i < 1024) ? b0[i] : b1[i - 1024];
}

// ---------------- LayerNorm over rows of length 1024 (in place, rounded) -------
__global__ __launch_bounds__(256)
void layernorm_k(float* __restrict__ x, const float* __restrict__ g,
                 const float* __restrict__ bt)
{
    __shared__ float sh[8];
    __shared__ float stat[2];
    float* row = x + (long long)blockIdx.x * 1024;
    const int tid  = threadIdx.x;
    const int lane = tid & 31;
    const int wid  = tid >> 5;

    float4 v = ((const float4*)row)[tid];

    float s = v.x + v.y + v.z + v.w;
#pragma unroll
    for (int o = 16; o > 0; o >>= 1) s += __shfl_xor_sync(0xffffffffu, s, o);
    if (lane == 0) sh[wid] = s;
    __syncthreads();
    if (wid == 0) {
        float t = (lane < 8) ? sh[lane] : 0.f;
#pragma unroll
        for (int o = 4; o > 0; o >>= 1) t += __shfl_xor_sync(0xffffffffu, t, o);
        if (lane == 0) stat[0] = t;
    }
    __syncthreads();
    const float mean = stat[0] * (1.f / 1024.f);

    const float dx = v.x - mean, dy = v.y - mean, dz = v.z - mean, dw = v.w - mean;
    float ss = dx * dx + dy * dy + dz * dz + dw * dw;
#pragma unroll
    for (int o = 16; o > 0; o >>= 1) ss += __shfl_xor_sync(0xffffffffu, ss, o);
    __syncthreads();
    if (lane == 0) sh[wid] = ss;
    __syncthreads();
    if (wid == 0) {
        float t = (lane < 8) ? sh[lane] : 0.f;
#pragma unroll
        for (int o = 4; o > 0; o >>= 1) t += __shfl_xor_sync(0xffffffffu, t, o);
        if (lane == 0) stat[1] = t;
    }
    __syncthreads();
    const float inv = rsqrtf(stat[1] * (1.f / 1024.f) + 1e-5f);

    const float4 gg = ((const float4*)g)[tid];
    const float4 bb = ((const float4*)bt)[tid];
    float4 o4;
    o4.x = tf32r(dx * inv * gg.x + bb.x);
    o4.y = tf32r(dy * inv * gg.y + bb.y);
    o4.z = tf32r(dz * inv * gg.z + bb.z);
    o4.w = tf32r(dw * inv * gg.w + bb.w);
    ((float4*)row)[tid] = o4;
}

// ---------------- tiled transpose: out[c, r] = in[r, c] (optional round) -------
__global__ __launch_bounds__(256)
void transpose_k(const float* __restrict__ in, int ldi, long long sIn,
                 float* __restrict__ out, int ldo, long long sOut, int rnd)
{
    __shared__ float t[32][33];
    in  += (long long)blockIdx.z * sIn;
    out += (long long)blockIdx.z * sOut;
    const int r0 = blockIdx.y * 32;
    const int c0 = blockIdx.x * 32;
    const int x = threadIdx.x;   // 32
    const int y = threadIdx.y;   // 8
#pragma unroll
    for (int i = 0; i < 32; i += 8)
        t[y + i][x] = in[(long long)(r0 + y + i) * ldi + c0 + x];
    __syncthreads();
    if (rnd) {
#pragma unroll
        for (int i = 0; i < 32; i += 8)
            out[(long long)(c0 + y + i) * ldo + r0 + x] = tf32r(t[x][y + i]);
    } else {
#pragma unroll
        for (int i = 0; i < 32; i += 8)
            out[(long long)(c0 + y + i) * ldo + r0 + x] = t[x][y + i];
    }
}

// ---------------- launcher ----------------
extern "C" void kernel_launch(void* const* d_in, const int* in_sizes, int n_in,
                              void* d_out, int out_size)
{
    const float* x_spa  = (const float*)d_in[0];
    const float* x_freq = (const float*)d_in[1];
    const float* w_cdc  = (const float*)d_in[2];
    const float* b_cdc  = (const float*)d_in[3];
    const float* w_sv   = (const float*)d_in[4];
    const float* b_sv   = (const float*)d_in[5];
    const float* w_fv   = (const float*)d_in[6];
    const float* b_fv   = (const float*)d_in[7];
    const float* ln_w   = (const float*)d_in[8];
    const float* ln_b   = (const float*)d_in[9];
    const float* w_qk   = (const float*)d_in[10];
    const float* w_spa  = (const float*)d_in[11];
    const float* b_spa  = (const float*)d_in[12];
    const float* w_frq  = (const float*)d_in[13];
    const float* b_frq  = (const float*)d_in[14];

    float* out_spa  = (float*)d_out;
    float* out_freq = (float*)d_out + (long long)NB * NC * HW;

    float *p_x, *p_vspa, *p_vfreq, *p_qk, *p_qT, *p_kw, *p_E, *p_part, *p_inv, *p_bcat;
    float *p_wqkT, *p_wspaT, *p_wfrqT;
    float *p_xspar, *p_xfreqr, *p_wcdcr, *p_wsvr, *p_wfvr;
    cudaGetSymbolAddress((void**)&p_x,      g_x);
    cudaGetSymbolAddress((void**)&p_vspa,   g_vspa);
    cudaGetSymbolAddress((void**)&p_vfreq,  g_vfreq);
    cudaGetSymbolAddress((void**)&p_qk,     g_qk);
    cudaGetSymbolAddress((void**)&p_qT,     g_qT);
    cudaGetSymbolAddress((void**)&p_kw,     g_kw);
    cudaGetSymbolAddress((void**)&p_E,      g_E);
    cudaGetSymbolAddress((void**)&p_part,   g_part);
    cudaGetSymbolAddress((void**)&p_inv,    g_inv);
    cudaGetSymbolAddress((void**)&p_bcat,   g_bcat);
    cudaGetSymbolAddress((void**)&p_wqkT,   g_wqkT);
    cudaGetSymbolAddress((void**)&p_wspaT,  g_wspaT);
    cudaGetSymbolAddress((void**)&p_wfrqT,  g_wfrqT);
    cudaGetSymbolAddress((void**)&p_xspar,  g_xspar);
    cudaGetSymbolAddress((void**)&p_xfreqr, g_xfreqr);
    cudaGetSymbolAddress((void**)&p_wcdcr,  g_wcdcr);
    cudaGetSymbolAddress((void**)&p_wsvr,   g_wsvr);
    cudaGetSymbolAddress((void**)&p_wfvr,   g_wfvr);

    static int smem_set = 0;
    if (!smem_set) {
        cudaFuncSetAttribute(sgemm_tc, cudaFuncAttributeMaxDynamicSharedMemorySize, SMEM_BYTES);
        smem_set = 1;
    }

    const long long sX   = (long long)NC * HW;        // 262144
    const long long sQK  = (long long)NC * 2 * HW;    // 524288
    const long long sQT  = (long long)HW * NC;        // 262144
    const long long sKW  = (long long)NC * 2 * HW;    // 524288
    const long long sE   = (long long)HW * 2 * HW;    // 2097152
    const dim3 tb(32, 8);
    const float scale = 0.03125f;                     // hw^-0.5 = 1/32
    const int BIGK = 1 << 30;

    // rounds
    round_k<<<(NB * NC * HW / 4 + 255) / 256, 256>>>((const float4*)x_spa,  (float4*)p_xspar,  NB * NC * HW / 4);
    round_k<<<(NB * NC * HW / 4 + 255) / 256, 256>>>((const float4*)x_freq, (float4*)p_xfreqr, NB * NC * HW / 4);
    round_k<<<(NC * 2 * NC / 4 + 255) / 256, 256>>>((const float4*)w_cdc, (float4*)p_wcdcr, NC * 2 * NC / 4);
    round_k<<<(NC * NC / 4 + 255) / 256, 256>>>((const float4*)w_sv, (float4*)p_wsvr, NC * NC / 4);
    round_k<<<(NC * NC / 4 + 255) / 256, 256>>>((const float4*)w_fv, (float4*)p_wfvr, NC * NC / 4);

    // merged cdc: X = w_cdc @ [x_spa; x_freq] + b_cdc    (M=256, N=1024, K=512)
    sgemm_tc<<<dim3(HW / BN, NC / BM, NB), 128, SMEM_BYTES>>>(
        p_wcdcr, 512, 0, p_xspar, 1024, sX, p_xfreqr, 256,
        nullptr, 0, b_cdc, nullptr, p_x, 1024, sX, 512, 1.f, 0, nullptr, nullptr);

    // v_spa / v_freq (rounded outputs)
    sgemm_tc<<<dim3(HW / BN, NC / BM, NB), 128, SMEM_BYTES>>>(
        p_wsvr, 256, 0, p_xspar, 1024, sX, nullptr, BIGK,
        nullptr, 0, b_sv, nullptr, p_vspa, 1024, sX, 256, 1.f, 1, nullptr, nullptr);
    sgemm_tc<<<dim3(HW / BN, NC / BM, NB), 128, SMEM_BYTES>>>(
        p_wfvr, 256, 0, p_xfreqr, 1024, sX, nullptr, BIGK,
        nullptr, 0, b_fv, nullptr, p_vfreq, 1024, sX, 256, 1.f, 1, nullptr, nullptr);

    // weight transposes (rounded) + bias concat
    transpose_k<<<dim3(1024 / 32, 2048 / 32, 1), tb>>>(w_qk, 1024, 0, p_wqkT, 2048, 0, 1);
    transpose_k<<<dim3(1024 / 32, 1024 / 32, 1), tb>>>(w_spa, 1024, 0, p_wspaT, 1024, 0, 1);
    transpose_k<<<dim3(1024 / 32, 1024 / 32, 1), tb>>>(w_frq, 1024, 0, p_wfrqT, 1024, 0, 1);
    bcat_k<<<8, 256>>>(b_spa, b_frq, p_bcat);

    // LayerNorm rows of X (rounds)
    layernorm_k<<<NB * NC, 256>>>(p_x, ln_w, ln_b);

    // qk GEMM: q half -> qT (transposed, rounded); k half -> g_qk cols 1024..
    sgemm_tc<<<dim3(2048 / BN, NC / BM, NB), 128, SMEM_BYTES>>>(
        p_x, 1024, sX, p_wqkT, 2048, 0, nullptr, BIGK,
        nullptr, 0, nullptr, nullptr, p_qk, 2048, sQK, 1024, 1.f, 1, nullptr, p_qT);

    // kw = k @ [w_spa^T | w_frq^T]  -> [256, 2048] per batch (rounded)
    sgemm_tc<<<dim3(HW / BN, NC / BM, NB), 128, SMEM_BYTES>>>(
        p_qk + 1024, 2048, sQK, p_wspaT, 1024, 0, nullptr, BIGK,
        nullptr, 0, nullptr, nullptr, p_kw, 2048, sKW, 1024, 1.f, 1, nullptr, nullptr);
    sgemm_tc<<<dim3(HW / BN, NC / BM, NB), 128, SMEM_BYTES>>>(
        p_qk + 1024, 2048, sQK, p_wfrqT, 1024, 0, nullptr, BIGK,
        nullptr, 0, nullptr, nullptr, p_kw + 1024, 2048, sKW, 1024, 1.f, 1, nullptr, nullptr);

    // E = exp(scale * qT @ kw + bcat)   [1024, 2048], K = 256, + row partials
    sgemm_tc<<<dim3(2048 / BN, HW / BM, NB), 128, SMEM_BYTES>>>(
        p_qT, 256, sQT, p_kw, 2048, sKW, nullptr, BIGK,
        nullptr, 0, nullptr, p_bcat, p_E, 2048, sE, 256, scale, 0, p_part, nullptr);

    // inverse row sums (deterministic)
    inv_k<<<(NB * 2 * HW + 255) / 256, 256>>>(p_part, p_inv, NB * 2 * HW);

    // v' = tf32r(v * inv)   (reuse x-round buffers, now free)
    vscale_k<<<NB * NC * HW / 4 / 256, 256>>>((const float4*)p_vspa,  p_inv,        (float4*)p_xspar);
    vscale_k<<<NB * NC * HW / 4 / 256, 256>>>((const float4*)p_vfreq, p_inv + 1024, (float4*)p_xfreqr);

    // final GEMMs: out = x + v' @ E_branch
    sgemm_tc<<<dim3(HW / BN, NC / BM, NB), 128, SMEM_BYTES>>>(
        p_xspar, 1024, sX, p_E, 2048, sE, nullptr, BIGK,
        x_spa, sX, nullptr, nullptr, out_spa, 1024, sX, 1024, 1.f, 0, nullptr, nullptr);
    sgemm_tc<<<dim3(HW / BN, NC / BM, NB), 128, SMEM_BYTES>>>(
        p_xfreqr, 1024, sX, p_E + 1024, 2048, sE, nullptr, BIGK,
        x_freq, sX, nullptr, nullptr, out_freq, 1024, sX, 1024, 1.f, 0, nullptr, nullptr);

    (void)in_sizes; (void)n_in; (void)out_size;
}

// round 15
// speedup vs baseline: 1.3027x; 1.3027x over previous
#include <cuda_runtime.h>
#include <cuda_fp16.h>
#include <cstdint>

// ---------------- problem constants ----------------
#define NB   16
#define NC   256
#define HW   1024
#define DIM  1024

// ---------------- fp32 scratch ----------------
__device__ float g_x[NB * NC * HW];            // cdc output fp32 (LN reads)
__device__ float g_vspa[NB * NC * HW];
__device__ float g_vfreq[NB * NC * HW];
__device__ float g_E[NB * HW * 2 * HW];        // exp(logits), tf32-rounded
__device__ float g_part[NB * 2 * HW * 16];
__device__ float g_inv[NB * 2 * HW];
__device__ float g_bcat[2 * HW];
__device__ float g_vs1[NB * NC * HW];          // v' = tf32r(v*inv)
__device__ float g_vs2[NB * NC * HW];

// ---------------- fp16 scratch ----------------
__device__ __half g_xTcat_h[NB * HW * 512];    // [b][n][512] = xT_spa | xT_freq
__device__ __half g_wcdc_h[NC * 2 * NC];
__device__ __half g_wsv_h[NC * NC];
__device__ __half g_wfv_h[NC * NC];
__device__ __half g_wqk_h[2 * DIM * DIM];      // w_qk as-is [2048][1024] = [n][k]
__device__ __half g_wcat_h[2 * DIM * DIM];     // [w_spa; w_frq]  [2048][1024]
__device__ __half g_xh[NB * NC * HW];          // LN output fp16
__device__ __half g_qk_h[NB * NC * 2 * HW];    // k half at cols 1024..
__device__ __half g_qT_h[NB * HW * NC];        // [b][n][c]
__device__ __half g_kwT_h[NB * 2 * HW * NC];   // [b][o'][c]

// ---------------- helpers ----------------
__device__ __forceinline__ float tf32r(float x) {
    asm("cvt.rna.tf32.f32 %0, %1;" : "=f"(x) : "f"(x));
    return x;
}
__device__ __forceinline__ void cpasync16(uint32_t dst, const void* src) {
    asm volatile("cp.async.cg.shared.global [%0], [%1], 16;\n" :: "r"(dst), "l"(src));
}
__device__ __forceinline__ void cpcommit() {
    asm volatile("cp.async.commit_group;\n");
}
__device__ __forceinline__ void cpwait1() {
    asm volatile("cp.async.wait_group 1;\n");
}
__device__ __forceinline__ void cpwait0() {
    asm volatile("cp.async.wait_group 0;\n");
}
__device__ __forceinline__ void mma_tf32(float* d, const uint32_t* a, const uint32_t* b) {
    asm volatile(
        "mma.sync.aligned.m16n8k8.row.col.f32.tf32.tf32.f32 "
        "{%0,%1,%2,%3}, {%4,%5,%6,%7}, {%8,%9}, {%0,%1,%2,%3};\n"
        : "+f"(d[0]), "+f"(d[1]), "+f"(d[2]), "+f"(d[3])
        : "r"(a[0]), "r"(a[1]), "r"(a[2]), "r"(a[3]), "r"(b[0]), "r"(b[1]));
}
__device__ __forceinline__ void mma_f16(float* d, const uint32_t* a, const uint32_t* b) {
    asm volatile(
        "mma.sync.aligned.m16n8k16.row.col.f32.f16.f16.f32 "
        "{%0,%1,%2,%3}, {%4,%5,%6,%7}, {%8,%9}, {%0,%1,%2,%3};\n"
        : "+f"(d[0]), "+f"(d[1]), "+f"(d[2]), "+f"(d[3])
        : "r"(a[0]), "r"(a[1]), "r"(a[2]), "r"(a[3]), "r"(b[0]), "r"(b[1]));
}

// =====================================================================
// fp16 tensor-core GEMM: C[m,n] = alpha * sum_k A[m,k]*B[n,k]  (B given [n][k])
// A,B __half. M%128==0, N%128==0, K%32==0.
// mode 0: C fp32 += biasRow (optional tf32 round)
// mode 1: C fp16
// mode 3: exp epilogue -> C fp32 tf32r(exp(clamp(alpha*acc + biasCol))) + partials
// qTp != nullptr && bn < 1024: write ONLY transposed fp16 qT[b][n][c]
// =====================================================================
#define BMH 128
#define BNH 128
#define BKH 32                         // halves of K per stage
#define LDH 40                         // halves per smem row (80B, 16B-aligned)
#define AH_HALVES (BMH * LDH)          // 5120
#define STAGEH_BYTES (2 * AH_HALVES * 2)   // A + B = 20480 B
#define NSTH 3
#define SMEMH_BYTES 66560              // >= 3*20480 and >= 128*129*4 (qT staging)

__global__ __launch_bounds__(128, 3)
void gemm_h(const __half* __restrict__ A, int lda, long long sA,
            const __half* __restrict__ B, int ldb, long long sB,
            const float* __restrict__ biasRow, const float* __restrict__ biasCol,
            void* __restrict__ Cp, int ldc, long long sC,
            int K, float alpha, int mode, int roundC,
            float* __restrict__ partials, __half* __restrict__ qTp)
{
    extern __shared__ float smem[];
    const uint32_t smem_u32 = (uint32_t)__cvta_generic_to_shared(smem);

    const long long bz = blockIdx.z;
    A += bz * sA;
    B += bz * sB;

    const int bm = blockIdx.y * BMH;
    const int bn = blockIdx.x * BNH;
    const int tid  = threadIdx.x;
    const int lane = tid & 31;
    const int wid  = tid >> 5;
    const int wm = wid >> 1;     // 0..1
    const int wn = wid & 1;      // 0..1
    const int rb = wm * 64;
    const int cb = wn * 64;
    const int lr = lane >> 2;    // 0..7
    const int lc = lane & 3;     // 0..3

    float acc[4][8][4];
#pragma unroll
    for (int i = 0; i < 4; i++)
#pragma unroll
        for (int j = 0; j < 8; j++)
#pragma unroll
            for (int v = 0; v < 4; v++) acc[i][j][v] = 0.f;

    const int l_row = tid >> 2;          // 0..31 (+32*u)  wait: 128 thr -> tid>>2 = 0..31
    const int l_ck  = tid & 3;           // chunk-of-4 within row

    const int T = K / BKH;

    auto load_stage = [&](int t, int s) {
        const int k0 = t * BKH;
        const uint32_t sa = smem_u32 + s * STAGEH_BYTES;
        const uint32_t sb = sa + AH_HALVES * 2;
#pragma unroll
        for (int u = 0; u < 4; u++) {
            const int row = l_row + u * 32;
            cpasync16(sa + row * 80 + l_ck * 16,
                      A + (long long)(bm + row) * lda + k0 + l_ck * 8);
        }
#pragma unroll
        for (int u = 0; u < 4; u++) {
            const int row = l_row + u * 32;
            cpasync16(sb + row * 80 + l_ck * 16,
                      B + (long long)(bn + row) * ldb + k0 + l_ck * 8);
        }
    };

    load_stage(0, 0); cpcommit();
    if (T > 1) { load_stage(1, 1); cpcommit(); }

    for (int t = 0; t < T; t++) {
        if (t < T - 1) cpwait1(); else cpwait0();
        __syncthreads();
        if (t + 2 < T) { load_stage(t + 2, (t + 2) % NSTH); }
        cpcommit();

        const char* sAc = (const char*)smem + (t % NSTH) * STAGEH_BYTES;
        const char* sBc = sAc + AH_HALVES * 2;

#pragma unroll
        for (int kk = 0; kk < 2; kk++) {        // two k16 steps per stage
            const int kb = kk * 16;
            uint32_t a[4][4];
#pragma unroll
            for (int mi = 0; mi < 4; mi++) {
                const int m0 = rb + mi * 16 + lr;
                a[mi][0] = *(const uint32_t*)(sAc + (m0 * LDH + kb + 2 * lc) * 2);
                a[mi][1] = *(const uint32_t*)(sAc + ((m0 + 8) * LDH + kb + 2 * lc) * 2);
                a[mi][2] = *(const uint32_t*)(sAc + (m0 * LDH + kb + 2 * lc + 8) * 2);
                a[mi][3] = *(const uint32_t*)(sAc + ((m0 + 8) * LDH + kb + 2 * lc + 8) * 2);
            }
            uint32_t b[8][2];
#pragma unroll
            for (int ni = 0; ni < 8; ni++) {
                const int n0 = cb + ni * 8 + lr;
                b[ni][0] = *(const uint32_t*)(sBc + (n0 * LDH + kb + 2 * lc) * 2);
                b[ni][1] = *(const uint32_t*)(sBc + (n0 * LDH + kb + 2 * lc + 8) * 2);
            }
#pragma unroll
            for (int mi = 0; mi < 4; mi++)
#pragma unroll
                for (int ni = 0; ni < 8; ni++)
                    mma_f16(acc[mi][ni], a[mi], b[ni]);
        }
        __syncthreads();
    }

    if (qTp && bn < 1024) {
        // stage fp32 tile, write fp16 transposed qT[b][n][c]
        float* s = smem;
#pragma unroll
        for (int mi = 0; mi < 4; mi++)
#pragma unroll
            for (int hh = 0; hh < 2; hh++) {
                const int rl = rb + mi * 16 + lr + hh * 8;
#pragma unroll
                for (int ni = 0; ni < 8; ni++) {
                    const int cl = cb + ni * 8 + lc * 2;
                    s[rl * 129 + cl]     = acc[mi][ni][hh * 2 + 0];
                    s[rl * 129 + cl + 1] = acc[mi][ni][hh * 2 + 1];
                }
            }
        __syncthreads();
        __half* qTb = qTp + bz * (long long)(HW * NC);
        for (int i = 0; i < 32; i++) {
            const int nl = wid * 32 + i;
            __half* row = qTb + (long long)(bn + nl) * 256 + bm;
#pragma unroll
            for (int u = 0; u < 4; u++)
                row[lane + 32 * u] = __float2half_rn(s[(lane + 32 * u) * 129 + nl]);
        }
        return;
    }

    if (mode == 3) {
        float* C = (float*)Cp + bz * sC;
        const int h = bn >> 10;
        const int slot = ((bn & 1023) + cb) >> 6;
#pragma unroll
        for (int mi = 0; mi < 4; mi++)
#pragma unroll
            for (int hh = 0; hh < 2; hh++) {
                const int r = bm + rb + mi * 16 + lr + hh * 8;
                const long long rowoff = (long long)r * ldc;
                float rowsum = 0.f;
#pragma unroll
                for (int ni = 0; ni < 8; ni++) {
                    const int c = bn + cb + ni * 8 + lc * 2;
                    const float2 bc = *(const float2*)(biasCol + c);
                    float f0 = alpha * acc[mi][ni][hh * 2 + 0] + bc.x;
                    float f1 = alpha * acc[mi][ni][hh * 2 + 1] + bc.y;
                    f0 = fminf(fmaxf(f0, -80.f), 80.f);
                    f1 = fminf(fmaxf(f1, -80.f), 80.f);
                    f0 = tf32r(__expf(f0));
                    f1 = tf32r(__expf(f1));
                    rowsum += f0 + f1;
                    float2 o; o.x = f0; o.y = f1;
                    *(float2*)(C + rowoff + c) = o;
                }
                rowsum += __shfl_xor_sync(0xffffffffu, rowsum, 1);
                rowsum += __shfl_xor_sync(0xffffffffu, rowsum, 2);
                if (lc == 0) {
                    const long long pidx =
                        (((long long)bz * 2048 + h * 1024 + r) << 4) + slot;
                    partials[pidx] = rowsum;
                }
            }
    } else if (mode == 1) {
        __half* C = (__half*)Cp + bz * sC;
#pragma unroll
        for (int mi = 0; mi < 4; mi++)
#pragma unroll
            for (int hh = 0; hh < 2; hh++) {
                const int r = bm + rb + mi * 16 + lr + hh * 8;
                const long long rowoff = (long long)r * ldc;
#pragma unroll
                for (int ni = 0; ni < 8; ni++) {
                    const int c = bn + cb + ni * 8 + lc * 2;
                    const float f0 = alpha * acc[mi][ni][hh * 2 + 0];
                    const float f1 = alpha * acc[mi][ni][hh * 2 + 1];
                    *(__half2*)(C + rowoff + c) = __floats2half2_rn(f0, f1);
                }
            }
    } else {
        float* C = (float*)Cp + bz * sC;
#pragma unroll
        for (int mi = 0; mi < 4; mi++)
#pragma unroll
            for (int hh = 0; hh < 2; hh++) {
                const int r = bm + rb + mi * 16 + lr + hh * 8;
                const float br = biasRow ? biasRow[r] : 0.f;
                const long long rowoff = (long long)r * ldc;
#pragma unroll
                for (int ni = 0; ni < 8; ni++) {
                    const int c = bn + cb + ni * 8 + lc * 2;
                    float f0 = alpha * acc[mi][ni][hh * 2 + 0] + br;
                    float f1 = alpha * acc[mi][ni][hh * 2 + 1] + br;
                    if (roundC) { f0 = tf32r(f0); f1 = tf32r(f1); }
                    float2 o; o.x = f0; o.y = f1;
                    *(float2*)(C + rowoff + c) = o;
                }
            }
    }
}

// =====================================================================
// tf32 GEMM (unchanged, round-14 proven) — used for the two final GEMMs
// =====================================================================
#define BM 128
#define BN 128
#define BKT 32
#define AS_LD 36
#define BS_LD 136
#define AS_FLOATS (BM * AS_LD)
#define BS_FLOATS (BKT * BS_LD)
#define STAGE_FLOATS (AS_FLOATS + BS_FLOATS)
#define STAGE_BYTES (STAGE_FLOATS * 4)
#define NSTAGES 2
#define SMEM_BYTES (STAGE_BYTES * NSTAGES)

__global__ __launch_bounds__(128, 3)
void sgemm_tc(const float* __restrict__ A, int lda, long long sA,
              const float* __restrict__ B, int ldb, long long sB,
              const float* __restrict__ Add, long long sAdd,
              float* __restrict__ C, int ldc, long long sC,
              int K, float alpha)
{
    extern __shared__ float smem[];
    const uint32_t smem_u32 = (uint32_t)__cvta_generic_to_shared(smem);

    const long long bz = blockIdx.z;
    A += bz * sA;
    B += bz * sB;
    C += bz * sC;
    if (Add) Add += bz * sAdd;

    const int bm = blockIdx.y * BM;
    const int bn = blockIdx.x * BN;
    const int tid  = threadIdx.x;
    const int lane = tid & 31;
    const int wid  = tid >> 5;
    const int wm = wid >> 1;
    const int wn = wid & 1;
    const int rb = wm * 64;
    const int cb = wn * 64;
    const int lr = lane >> 2;
    const int lc = lane & 3;

    float acc[4][8][4];
#pragma unroll
    for (int i = 0; i < 4; i++)
#pragma unroll
        for (int j = 0; j < 8; j++)
#pragma unroll
            for (int v = 0; v < 4; v++) acc[i][j][v] = 0.f;

    const int a_row = tid >> 3;
    const int a_k4  = (tid & 7) * 4;
    const int b_row = tid >> 5;
    const int b_n4  = (tid & 31) * 4;

    const int T = K / BKT;

    auto load_stage = [&](int t, int s) {
        const int k0 = t * BKT;
        const uint32_t sa = smem_u32 + s * STAGE_BYTES;
        const uint32_t sb = sa + AS_FLOATS * 4;
#pragma unroll
        for (int u = 0; u < 8; u++) {
            const int r = a_row + u * 16;
            cpasync16(sa + (r * AS_LD + a_k4) * 4,
                      A + (long long)(bm + r) * lda + k0 + a_k4);
        }
#pragma unroll
        for (int u = 0; u < 8; u++) {
            const int r = b_row + u * 4;
            cpasync16(sb + (r * BS_LD + b_n4) * 4,
                      B + (long long)(k0 + r) * ldb + bn + b_n4);
        }
    };

    load_stage(0, 0); cpcommit();

    for (int t = 0; t < T; t++) {
        if (t + 1 < T) {
            load_stage(t + 1, (t + 1) & 1);
            cpcommit();
            cpwait1();
        } else {
            cpwait0();
        }
        __syncthreads();

        const float* sA_ = smem + (t & 1) * STAGE_FLOATS;
        const float* sB_ = sA_ + AS_FLOATS;

#pragma unroll
        for (int kk = 0; kk < 4; kk++) {
            const int kb = kk * 8 + lc;
            uint32_t a[4][4];
#pragma unroll
            for (int mi = 0; mi < 4; mi++) {
                const int m0 = rb + mi * 16 + lr;
                a[mi][0] = __float_as_uint(sA_[m0 * AS_LD + kb]);
                a[mi][1] = __float_as_uint(sA_[(m0 + 8) * AS_LD + kb]);
                a[mi][2] = __float_as_uint(sA_[m0 * AS_LD + kb + 4]);
                a[mi][3] = __float_as_uint(sA_[(m0 + 8) * AS_LD + kb + 4]);
            }
            uint32_t b[8][2];
#pragma unroll
            for (int ni = 0; ni < 8; ni++) {
                const int n0 = cb + ni * 8 + lr;
                b[ni][0] = __float_as_uint(sB_[kb * BS_LD + n0]);
                b[ni][1] = __float_as_uint(sB_[(kb + 4) * BS_LD + n0]);
            }
#pragma unroll
            for (int mi = 0; mi < 4; mi++)
#pragma unroll
                for (int ni = 0; ni < 8; ni++)
                    mma_tf32(acc[mi][ni], a[mi], b[ni]);
        }
        __syncthreads();
    }

#pragma unroll
    for (int mi = 0; mi < 4; mi++)
#pragma unroll
        for (int hh = 0; hh < 2; hh++) {
            const int r = bm + rb + mi * 16 + lr + hh * 8;
            const long long rowoff = (long long)r * ldc;
#pragma unroll
            for (int ni = 0; ni < 8; ni++) {
                const int c = bn + cb + ni * 8 + lc * 2;
                float f0 = alpha * acc[mi][ni][hh * 2 + 0];
                float f1 = alpha * acc[mi][ni][hh * 2 + 1];
                if (Add) {
                    const float2 ad = *(const float2*)(Add + rowoff + c);
                    f0 += ad.x; f1 += ad.y;
                }
                float2 o; o.x = f0; o.y = f1;
                *(float2*)(C + rowoff + c) = o;
            }
        }
}

// ---------------- elementwise kernels ----------------
__global__ __launch_bounds__(256)
void round_h_k(const float4* __restrict__ in, __half2* __restrict__ out, int n4)
{
    int i = blockIdx.x * 256 + threadIdx.x;
    if (i < n4) {
        float4 v = in[i];
        out[2 * i]     = __floats2half2_rn(v.x, v.y);
        out[2 * i + 1] = __floats2half2_rn(v.z, v.w);
    }
}

// transpose fp32 -> fp16: out[c][r] = in[r][c]
__global__ __launch_bounds__(256)
void transpose_h_k(const float* __restrict__ in, int ldi, long long sIn,
                   __half* __restrict__ out, int ldo, long long sOut)
{
    __shared__ float t[32][33];
    in  += (long long)blockIdx.z * sIn;
    out += (long long)blockIdx.z * sOut;
    const int r0 = blockIdx.y * 32;
    const int c0 = blockIdx.x * 32;
    const int x = threadIdx.x;
    const int y = threadIdx.y;
#pragma unroll
    for (int i = 0; i < 32; i += 8)
        t[y + i][x] = in[(long long)(r0 + y + i) * ldi + c0 + x];
    __syncthreads();
#pragma unroll
    for (int i = 0; i < 32; i += 8)
        out[(long long)(c0 + y + i) * ldo + r0 + x] = __float2half_rn(t[x][y + i]);
}

// LayerNorm rows of 1024: read fp32 x, write fp16 out
__global__ __launch_bounds__(256)
void layernorm_h_k(const float* __restrict__ x, __half* __restrict__ xh,
                   const float* __restrict__ g, const float* __restrict__ bt)
{
    __shared__ float sh[8];
    __shared__ float stat[2];
    const float* row = x + (long long)blockIdx.x * 1024;
    __half2* ro = (__half2*)(xh + (long long)blockIdx.x * 1024);
    const int tid  = threadIdx.x;
    const int lane = tid & 31;
    const int wid  = tid >> 5;

    float4 v = ((const float4*)row)[tid];

    float s = v.x + v.y + v.z + v.w;
#pragma unroll
    for (int o = 16; o > 0; o >>= 1) s += __shfl_xor_sync(0xffffffffu, s, o);
    if (lane == 0) sh[wid] = s;
    __syncthreads();
    if (wid == 0) {
        float t = (lane < 8) ? sh[lane] : 0.f;
#pragma unroll
        for (int o = 4; o > 0; o >>= 1) t += __shfl_xor_sync(0xffffffffu, t, o);
        if (lane == 0) stat[0] = t;
    }
    __syncthreads();
    const float mean = stat[0] * (1.f / 1024.f);

    const float dx = v.x - mean, dy = v.y - mean, dz = v.z - mean, dw = v.w - mean;
    float ss = dx * dx + dy * dy + dz * dz + dw * dw;
#pragma unroll
    for (int o = 16; o > 0; o >>= 1) ss += __shfl_xor_sync(0xffffffffu, ss, o);
    __syncthreads();
    if (lane == 0) sh[wid] = ss;
    __syncthreads();
    if (wid == 0) {
        float t = (lane < 8) ? sh[lane] : 0.f;
#pragma unroll
        for (int o = 4; o > 0; o >>= 1) t += __shfl_xor_sync(0xffffffffu, t, o);
        if (lane == 0) stat[1] = t;
    }
    __syncthreads();
    const float inv = rsqrtf(stat[1] * (1.f / 1024.f) + 1e-5f);

    const float4 gg = ((const float4*)g)[tid];
    const float4 bb = ((const float4*)bt)[tid];
    ro[tid * 2]     = __floats2half2_rn(dx * inv * gg.x + bb.x, dy * inv * gg.y + bb.y);
    ro[tid * 2 + 1] = __floats2half2_rn(dz * inv * gg.z + bb.z, dw * inv * gg.w + bb.w);
}

__global__ __launch_bounds__(256)
void inv_k(const float* __restrict__ part, float* __restrict__ inv, int n)
{
    int i = blockIdx.x * 256 + threadIdx.x;
    if (i < n) {
        const float4* p = (const float4*)(part + ((long long)i << 4));
        float4 a = p[0], b = p[1], c = p[2], d = p[3];
        float s = ((a.x + a.y) + (a.z + a.w)) + ((b.x + b.y) + (b.z + b.w))
                + ((c.x + c.y) + (c.z + c.w)) + ((d.x + d.y) + (d.z + d.w));
        inv[i] = 1.f / s;
    }
}

__global__ __launch_bounds__(256)
void bcat_k(const float* __restrict__ b0, const float* __restrict__ b1,
            float* __restrict__ out)
{
    int i = blockIdx.x * 256 + threadIdx.x;
    if (i < 2048) out[i] = (i < 1024) ? b0[i] : b1[i - 1024];
}

// v' = tf32r(v * inv[n])
__global__ __launch_bounds__(256)
void vscale_k(const float4* __restrict__ v, const float* __restrict__ inv,
              float4* __restrict__ out)
{
    const long long i = (long long)blockIdx.x * 256 + threadIdx.x;
    const int b  = (int)(i >> 16);
    const int n4 = (int)(i & 255);
    float4 vv = v[i];
    const float4 iv = *(const float4*)(inv + (long long)b * 2048 + n4 * 4);
    vv.x = tf32r(vv.x * iv.x);
    vv.y = tf32r(vv.y * iv.y);
    vv.z = tf32r(vv.z * iv.z);
    vv.w = tf32r(vv.w * iv.w);
    out[i] = vv;
}

// ---------------- launcher ----------------
extern "C" void kernel_launch(void* const* d_in, const int* in_sizes, int n_in,
                              void* d_out, int out_size)
{
    const float* x_spa  = (const float*)d_in[0];
    const float* x_freq = (const float*)d_in[1];
    const float* w_cdc  = (const float*)d_in[2];
    const float* b_cdc  = (const float*)d_in[3];
    const float* w_sv   = (const float*)d_in[4];
    const float* b_sv   = (const float*)d_in[5];
    const float* w_fv   = (const float*)d_in[6];
    const float* b_fv   = (const float*)d_in[7];
    const float* ln_w   = (const float*)d_in[8];
    const float* ln_b   = (const float*)d_in[9];
    const float* w_qk   = (const float*)d_in[10];
    const float* w_spa  = (const float*)d_in[11];
    const float* b_spa  = (const float*)d_in[12];
    const float* w_frq  = (const float*)d_in[13];
    const float* b_frq  = (const float*)d_in[14];

    float* out_spa  = (float*)d_out;
    float* out_freq = (float*)d_out + (long long)NB * NC * HW;

    float *p_x, *p_vspa, *p_vfreq, *p_E, *p_part, *p_inv, *p_bcat, *p_vs1, *p_vs2;
    __half *p_xTcat, *p_wcdc, *p_wsv, *p_wfv, *p_wqk, *p_wcat, *p_xh, *p_qkh, *p_qTh, *p_kwTh;
    cudaGetSymbolAddress((void**)&p_x,     g_x);
    cudaGetSymbolAddress((void**)&p_vspa,  g_vspa);
    cudaGetSymbolAddress((void**)&p_vfreq, g_vfreq);
    cudaGetSymbolAddress((void**)&p_E,     g_E);
    cudaGetSymbolAddress((void**)&p_part,  g_part);
    cudaGetSymbolAddress((void**)&p_inv,   g_inv);
    cudaGetSymbolAddress((void**)&p_bcat,  g_bcat);
    cudaGetSymbolAddress((void**)&p_vs1,   g_vs1);
    cudaGetSymbolAddress((void**)&p_vs2,   g_vs2);
    cudaGetSymbolAddress((void**)&p_xTcat, g_xTcat_h);
    cudaGetSymbolAddress((void**)&p_wcdc,  g_wcdc_h);
    cudaGetSymbolAddress((void**)&p_wsv,   g_wsv_h);
    cudaGetSymbolAddress((void**)&p_wfv,   g_wfv_h);
    cudaGetSymbolAddress((void**)&p_wqk,   g_wqk_h);
    cudaGetSymbolAddress((void**)&p_wcat,  g_wcat_h);
    cudaGetSymbolAddress((void**)&p_xh,    g_xh);
    cudaGetSymbolAddress((void**)&p_qkh,   g_qk_h);
    cudaGetSymbolAddress((void**)&p_qTh,   g_qT_h);
    cudaGetSymbolAddress((void**)&p_kwTh,  g_kwT_h);

    static int smem_set = 0;
    if (!smem_set) {
        cudaFuncSetAttribute(gemm_h,   cudaFuncAttributeMaxDynamicSharedMemorySize, SMEMH_BYTES);
        cudaFuncSetAttribute(sgemm_tc, cudaFuncAttributeMaxDynamicSharedMemorySize, SMEM_BYTES);
        smem_set = 1;
    }

    const long long sX   = (long long)NC * HW;      // 262144
    const long long sXT  = (long long)HW * 512;
    const long long sQKh = (long long)NC * 2 * HW;
    const long long sQTh = (long long)HW * NC;
    const long long sKWT = (long long)2 * HW * NC;
    const long long sE   = (long long)HW * 2 * HW;
    const dim3 tb(32, 8);
    const float scale = 0.03125f;

    // xTcat = [x_spa^T | x_freq^T] fp16   [b][1024][512]
    transpose_h_k<<<dim3(HW / 32, NC / 32, NB), tb>>>(x_spa, 1024, sX, p_xTcat, 512, sXT);
    transpose_h_k<<<dim3(HW / 32, NC / 32, NB), tb>>>(x_freq, 1024, sX, p_xTcat + 256, 512, sXT);

    // weight rounds -> fp16
    round_h_k<<<(NC * 2 * NC / 4 + 255) / 256, 256>>>((const float4*)w_cdc, (__half2*)p_wcdc, NC * 2 * NC / 4);
    round_h_k<<<(NC * NC / 4 + 255) / 256, 256>>>((const float4*)w_sv, (__half2*)p_wsv, NC * NC / 4);
    round_h_k<<<(NC * NC / 4 + 255) / 256, 256>>>((const float4*)w_fv, (__half2*)p_wfv, NC * NC / 4);

    // cdc: X = w_cdc @ [x_spa; x_freq] + b_cdc   M=256 N=1024 K=512, fp32 out
    gemm_h<<<dim3(HW / BNH, NC / BMH, NB), 128, SMEMH_BYTES>>>(
        p_wcdc, 512, 0, p_xTcat, 512, sXT, b_cdc, nullptr,
        p_x, 1024, sX, 512, 1.f, 0, 0, nullptr, nullptr);

    // v_spa / v_freq: fp32 out (vscale rounds later)
    gemm_h<<<dim3(HW / BNH, NC / BMH, NB), 128, SMEMH_BYTES>>>(
        p_wsv, 256, 0, p_xTcat, 512, sXT, b_sv, nullptr,
        p_vspa, 1024, sX, 256, 1.f, 0, 0, nullptr, nullptr);
    gemm_h<<<dim3(HW / BNH, NC / BMH, NB), 128, SMEMH_BYTES>>>(
        p_wfv, 256, 0, p_xTcat + 256, 512, sXT, b_fv, nullptr,
        p_vfreq, 1024, sX, 256, 1.f, 0, 0, nullptr, nullptr);

    // more weight rounds + bias concat
    round_h_k<<<(2 * DIM * DIM / 4 + 255) / 256, 256>>>((const float4*)w_qk, (__half2*)p_wqk, 2 * DIM * DIM / 4);
    round_h_k<<<(DIM * DIM / 4 + 255) / 256, 256>>>((const float4*)w_spa, (__half2*)p_wcat, DIM * DIM / 4);
    round_h_k<<<(DIM * DIM / 4 + 255) / 256, 256>>>((const float4*)w_frq, (__half2*)(p_wcat + DIM * DIM), DIM * DIM / 4);
    bcat_k<<<8, 256>>>(b_spa, b_frq, p_bcat);

    // LN: fp32 X -> fp16 Xh
    layernorm_h_k<<<NB * NC, 256>>>(p_x, p_xh, ln_w, ln_b);

    // qk: A=Xh [256,1024], B=w_qk [2048,1024]; q half -> qT_h transposed, k half -> g_qk_h
    gemm_h<<<dim3(2048 / BNH, NC / BMH, NB), 128, SMEMH_BYTES>>>(
        p_xh, 1024, sX, p_wqk, 1024, 0, nullptr, nullptr,
        p_qkh, 2048, sQKh, 1024, 1.f, 1, 0, nullptr, p_qTh);

    // kwT = wcat @ k^T: A=wcat [2048,1024] shared, B=k_h [256 n,1024 k] (ld 2048)
    gemm_h<<<dim3(NC / BNH, 2 * HW / BMH, NB), 128, SMEMH_BYTES>>>(
        p_wcat, 1024, 0, p_qkh + 1024, 2048, sQKh, nullptr, nullptr,
        p_kwTh, 256, sKWT, 1024, 1.f, 1, 0, nullptr, nullptr);

    // E = exp(scale * qT @ kwT^T + bcat): A=qT_h [1024,256], B=kwT_h [2048,256]
    gemm_h<<<dim3(2048 / BNH, HW / BMH, NB), 128, SMEMH_BYTES>>>(
        p_qTh, 256, sQTh, p_kwTh, 256, sKWT, nullptr, p_bcat,
        p_E, 2048, sE, 256, scale, 3, 0, p_part, nullptr);

    // inverse row sums
    inv_k<<<(NB * 2 * HW + 255) / 256, 256>>>(p_part, p_inv, NB * 2 * HW);

    // v' = tf32r(v * inv)
    vscale_k<<<NB * NC * HW / 4 / 256, 256>>>((const float4*)p_vspa,  p_inv,        (float4*)p_vs1);
    vscale_k<<<NB * NC * HW / 4 / 256, 256>>>((const float4*)p_vfreq, p_inv + 1024, (float4*)p_vs2);

    // final tf32 GEMMs: out = x + v' @ E_branch
    sgemm_tc<<<dim3(HW / BN, NC / BM, NB), 128, SMEM_BYTES>>>(
        p_vs1, 1024, sX, p_E, 2048, sE, x_spa, sX,
        out_spa, 1024, sX, 1024, 1.f);
    sgemm_tc<<<dim3(HW / BN, NC / BM, NB), 128, SMEM_BYTES>>>(
        p_vs2, 1024, sX, p_E + 1024, 2048, sE, x_freq, sX,
        out_freq, 1024, sX, 1024, 1.f);

    (void)in_sizes; (void)n_in; (void)out_size;
}

// round 16
// speedup vs baseline: 1.4138x; 1.0853x over previous
#include <cuda_runtime.h>
#include <cuda_fp16.h>
#include <cstdint>

// ---------------- problem constants ----------------
#define NB   16
#define NC   256
#define HW   1024
#define DIM  1024

// ---------------- fp32 scratch ----------------
__device__ float g_x[NB * NC * HW];            // cdc output fp32 (LN reads)
__device__ float g_vspa[NB * NC * HW];
__device__ float g_vfreq[NB * NC * HW];
__device__ float g_part[NB * 2 * HW * 16];
__device__ float g_inv[NB * 2 * HW];
__device__ float g_bcat[2 * HW];

// ---------------- fp16 scratch ----------------
__device__ __half g_xTcat_h[NB * HW * 512];    // [b][n][512] = xT_spa | xT_freq
__device__ __half g_wcdc_h[NC * 2 * NC];
__device__ __half g_wsv_h[NC * NC];
__device__ __half g_wfv_h[NC * NC];
__device__ __half g_wqk_h[2 * DIM * DIM];      // [2048][1024] = [n][k]
__device__ __half g_wcat_h[2 * DIM * DIM];     // [w_spa; w_frq]
__device__ __half g_xh[NB * NC * HW];          // LN output fp16
__device__ __half g_qk_h[NB * NC * 2 * HW];    // k half at cols 1024..
__device__ __half g_qT_h[NB * HW * NC];        // [b][n][c]
__device__ __half g_kwT_h[NB * 2 * HW * NC];   // [b][o'][c]
__device__ __half g_ET_h[NB * 2 * HW * HW];    // [b][o(2048)][n(1024)] exp transposed
__device__ __half g_vs1_h[NB * NC * HW];       // v'_spa fp16
__device__ __half g_vs2_h[NB * NC * HW];       // v'_freq fp16

// ---------------- helpers ----------------
__device__ __forceinline__ float tf32r(float x) {
    asm("cvt.rna.tf32.f32 %0, %1;" : "=f"(x) : "f"(x));
    return x;
}
__device__ __forceinline__ void cpasync16(uint32_t dst, const void* src) {
    asm volatile("cp.async.cg.shared.global [%0], [%1], 16;\n" :: "r"(dst), "l"(src));
}
__device__ __forceinline__ void cpcommit() {
    asm volatile("cp.async.commit_group;\n");
}
__device__ __forceinline__ void cpwait1() {
    asm volatile("cp.async.wait_group 1;\n");
}
__device__ __forceinline__ void cpwait0() {
    asm volatile("cp.async.wait_group 0;\n");
}
__device__ __forceinline__ void mma_f16(float* d, const uint32_t* a, const uint32_t* b) {
    asm volatile(
        "mma.sync.aligned.m16n8k16.row.col.f32.f16.f16.f32 "
        "{%0,%1,%2,%3}, {%4,%5,%6,%7}, {%8,%9}, {%0,%1,%2,%3};\n"
        : "+f"(d[0]), "+f"(d[1]), "+f"(d[2]), "+f"(d[3])
        : "r"(a[0]), "r"(a[1]), "r"(a[2]), "r"(a[3]), "r"(b[0]), "r"(b[1]));
}

// =====================================================================
// fp16 tensor-core GEMM: C[m,n] = alpha * sum_k A[m,k]*B[n,k]  (B given [n][k])
// mode 0: C fp32 = acc + biasRow
// mode 1: C fp16
// mode 3: exp epilogue -> ET fp16 TRANSPOSED ([o][n], fixed ld 1024) + partials
// mode 4: C fp32 = acc + Add (residual)
// qTp != nullptr && bn < 1024: write ONLY transposed fp16 qT[b][n][c]
// =====================================================================
#define BMH 128
#define BNH 128
#define BKH 32
#define LDH 40                         // halves per smem row (80B)
#define AH_HALVES (BMH * LDH)          // 5120
#define STAGEH_BYTES (2 * AH_HALVES * 2)   // 20480
#define NSTH 3
#define SMEMH_BYTES 66560              // >= 3 stages, >= 128*129*4 staging

__global__ __launch_bounds__(128, 3)
void gemm_h(const __half* __restrict__ A, int lda, long long sA,
            const __half* __restrict__ B, int ldb, long long sB,
            const float* __restrict__ biasRow, const float* __restrict__ biasCol,
            const float* __restrict__ Add, long long sAdd,
            void* __restrict__ Cp, int ldc, long long sC,
            int K, float alpha, int mode,
            float* __restrict__ partials, __half* __restrict__ qTp)
{
    extern __shared__ float smem[];
    const uint32_t smem_u32 = (uint32_t)__cvta_generic_to_shared(smem);

    const long long bz = blockIdx.z;
    A += bz * sA;
    B += bz * sB;
    if (Add) Add += bz * sAdd;

    const int bm = blockIdx.y * BMH;
    const int bn = blockIdx.x * BNH;
    const int tid  = threadIdx.x;
    const int lane = tid & 31;
    const int wid  = tid >> 5;
    const int wm = wid >> 1;
    const int wn = wid & 1;
    const int rb = wm * 64;
    const int cb = wn * 64;
    const int lr = lane >> 2;
    const int lc = lane & 3;

    float acc[4][8][4];
#pragma unroll
    for (int i = 0; i < 4; i++)
#pragma unroll
        for (int j = 0; j < 8; j++)
#pragma unroll
            for (int v = 0; v < 4; v++) acc[i][j][v] = 0.f;

    const int l_row = tid >> 2;          // 0..31
    const int l_ck  = tid & 3;

    const int T = K / BKH;

    auto load_stage = [&](int t, int s) {
        const int k0 = t * BKH;
        const uint32_t sa = smem_u32 + s * STAGEH_BYTES;
        const uint32_t sb = sa + AH_HALVES * 2;
#pragma unroll
        for (int u = 0; u < 4; u++) {
            const int row = l_row + u * 32;
            cpasync16(sa + row * 80 + l_ck * 16,
                      A + (long long)(bm + row) * lda + k0 + l_ck * 8);
        }
#pragma unroll
        for (int u = 0; u < 4; u++) {
            const int row = l_row + u * 32;
            cpasync16(sb + row * 80 + l_ck * 16,
                      B + (long long)(bn + row) * ldb + k0 + l_ck * 8);
        }
    };

    load_stage(0, 0); cpcommit();
    if (T > 1) { load_stage(1, 1); cpcommit(); }

    for (int t = 0; t < T; t++) {
        if (t < T - 1) cpwait1(); else cpwait0();
        __syncthreads();
        if (t + 2 < T) { load_stage(t + 2, (t + 2) % NSTH); }
        cpcommit();

        const char* sAc = (const char*)smem + (t % NSTH) * STAGEH_BYTES;
        const char* sBc = sAc + AH_HALVES * 2;

#pragma unroll
        for (int kk = 0; kk < 2; kk++) {
            const int kb = kk * 16;
            uint32_t a[4][4];
#pragma unroll
            for (int mi = 0; mi < 4; mi++) {
                const int m0 = rb + mi * 16 + lr;
                a[mi][0] = *(const uint32_t*)(sAc + (m0 * LDH + kb + 2 * lc) * 2);
                a[mi][1] = *(const uint32_t*)(sAc + ((m0 + 8) * LDH + kb + 2 * lc) * 2);
                a[mi][2] = *(const uint32_t*)(sAc + (m0 * LDH + kb + 2 * lc + 8) * 2);
                a[mi][3] = *(const uint32_t*)(sAc + ((m0 + 8) * LDH + kb + 2 * lc + 8) * 2);
            }
            uint32_t b[8][2];
#pragma unroll
            for (int ni = 0; ni < 8; ni++) {
                const int n0 = cb + ni * 8 + lr;
                b[ni][0] = *(const uint32_t*)(sBc + (n0 * LDH + kb + 2 * lc) * 2);
                b[ni][1] = *(const uint32_t*)(sBc + (n0 * LDH + kb + 2 * lc + 8) * 2);
            }
#pragma unroll
            for (int mi = 0; mi < 4; mi++)
#pragma unroll
                for (int ni = 0; ni < 8; ni++)
                    mma_f16(acc[mi][ni], a[mi], b[ni]);
        }
        __syncthreads();
    }

    if (qTp && bn < 1024) {
        // q half: stage fp32 tile, write fp16 transposed qT[b][n][c]
        float* s = smem;
#pragma unroll
        for (int mi = 0; mi < 4; mi++)
#pragma unroll
            for (int hh = 0; hh < 2; hh++) {
                const int rl = rb + mi * 16 + lr + hh * 8;
#pragma unroll
                for (int ni = 0; ni < 8; ni++) {
                    const int cl = cb + ni * 8 + lc * 2;
                    s[rl * 129 + cl]     = acc[mi][ni][hh * 2 + 0];
                    s[rl * 129 + cl + 1] = acc[mi][ni][hh * 2 + 1];
                }
            }
        __syncthreads();
        __half* qTb = qTp + bz * (long long)(HW * NC);
        for (int i = 0; i < 32; i++) {
            const int nl = wid * 32 + i;
            __half* row = qTb + (long long)(bn + nl) * 256 + bm;
#pragma unroll
            for (int u = 0; u < 4; u++)
                row[lane + 32 * u] = __float2half_rn(s[(lane + 32 * u) * 129 + nl]);
        }
        return;
    }

    if (mode == 3) {
        // exp epilogue: partials + TRANSPOSED fp16 store ET[o][n]
        __half* ET = (__half*)Cp + bz * sC;
        const int h = bn >> 10;
        const int slot = ((bn & 1023) + cb) >> 6;
        float* s = smem;
#pragma unroll
        for (int mi = 0; mi < 4; mi++)
#pragma unroll
            for (int hh = 0; hh < 2; hh++) {
                const int rl = rb + mi * 16 + lr + hh * 8;   // local n row
                const int r = bm + rl;                        // global n
                float rowsum = 0.f;
#pragma unroll
                for (int ni = 0; ni < 8; ni++) {
                    const int cl = cb + ni * 8 + lc * 2;      // local o col
                    const float2 bc = *(const float2*)(biasCol + bn + cl);
                    float f0 = alpha * acc[mi][ni][hh * 2 + 0] + bc.x;
                    float f1 = alpha * acc[mi][ni][hh * 2 + 1] + bc.y;
                    f0 = fminf(fmaxf(f0, -15.f), 11.f);
                    f1 = fminf(fmaxf(f1, -15.f), 11.f);
                    const __half h0 = __float2half_rn(__expf(f0));
                    const __half h1 = __float2half_rn(__expf(f1));
                    const float e0 = __half2float(h0);
                    const float e1 = __half2float(h1);
                    rowsum += e0 + e1;
                    s[rl * 129 + cl]     = e0;
                    s[rl * 129 + cl + 1] = e1;
                }
                rowsum += __shfl_xor_sync(0xffffffffu, rowsum, 1);
                rowsum += __shfl_xor_sync(0xffffffffu, rowsum, 2);
                if (lc == 0) {
                    const long long pidx =
                        (((long long)bz * 2048 + h * 1024 + r) << 4) + slot;
                    partials[pidx] = rowsum;
                }
            }
        __syncthreads();
        // write ET rows: o = bn + ol, n = bm + 0..127 (half2 coalesced)
        for (int i = 0; i < 32; i++) {
            const int ol = wid * 32 + i;
            __half2* row = (__half2*)(ET + (long long)(bn + ol) * 1024 + bm);
#pragma unroll
            for (int u = 0; u < 2; u++) {
                const int nl = 2 * lane + 64 * u;
                row[lane + 32 * u] = __floats2half2_rn(s[nl * 129 + ol],
                                                       s[(nl + 1) * 129 + ol]);
            }
        }
        return;
    }

    if (mode == 1) {
        __half* C = (__half*)Cp + bz * sC;
#pragma unroll
        for (int mi = 0; mi < 4; mi++)
#pragma unroll
            for (int hh = 0; hh < 2; hh++) {
                const int r = bm + rb + mi * 16 + lr + hh * 8;
                const long long rowoff = (long long)r * ldc;
#pragma unroll
                for (int ni = 0; ni < 8; ni++) {
                    const int c = bn + cb + ni * 8 + lc * 2;
                    *(__half2*)(C + rowoff + c) =
                        __floats2half2_rn(alpha * acc[mi][ni][hh * 2 + 0],
                                          alpha * acc[mi][ni][hh * 2 + 1]);
                }
            }
    } else if (mode == 4) {
        float* C = (float*)Cp + bz * sC;
#pragma unroll
        for (int mi = 0; mi < 4; mi++)
#pragma unroll
            for (int hh = 0; hh < 2; hh++) {
                const int r = bm + rb + mi * 16 + lr + hh * 8;
                const long long rowoff = (long long)r * ldc;
#pragma unroll
                for (int ni = 0; ni < 8; ni++) {
                    const int c = bn + cb + ni * 8 + lc * 2;
                    const float2 ad = *(const float2*)(Add + rowoff + c);
                    float2 o;
                    o.x = acc[mi][ni][hh * 2 + 0] + ad.x;
                    o.y = acc[mi][ni][hh * 2 + 1] + ad.y;
                    *(float2*)(C + rowoff + c) = o;
                }
            }
    } else {
        float* C = (float*)Cp + bz * sC;
#pragma unroll
        for (int mi = 0; mi < 4; mi++)
#pragma unroll
            for (int hh = 0; hh < 2; hh++) {
                const int r = bm + rb + mi * 16 + lr + hh * 8;
                const float br = biasRow ? biasRow[r] : 0.f;
                const long long rowoff = (long long)r * ldc;
#pragma unroll
                for (int ni = 0; ni < 8; ni++) {
                    const int c = bn + cb + ni * 8 + lc * 2;
                    float2 o;
                    o.x = acc[mi][ni][hh * 2 + 0] + br;
                    o.y = acc[mi][ni][hh * 2 + 1] + br;
                    *(float2*)(C + rowoff + c) = o;
                }
            }
    }
}

// ---------------- elementwise kernels ----------------
__global__ __launch_bounds__(256)
void round_h_k(const float4* __restrict__ in, __half2* __restrict__ out, int n4)
{
    int i = blockIdx.x * 256 + threadIdx.x;
    if (i < n4) {
        float4 v = in[i];
        out[2 * i]     = __floats2half2_rn(v.x, v.y);
        out[2 * i + 1] = __floats2half2_rn(v.z, v.w);
    }
}

// transpose fp32 -> fp16
__global__ __launch_bounds__(256)
void transpose_h_k(const float* __restrict__ in, int ldi, long long sIn,
                   __half* __restrict__ out, int ldo, long long sOut)
{
    __shared__ float t[32][33];
    in  += (long long)blockIdx.z * sIn;
    out += (long long)blockIdx.z * sOut;
    const int r0 = blockIdx.y * 32;
    const int c0 = blockIdx.x * 32;
    const int x = threadIdx.x;
    const int y = threadIdx.y;
#pragma unroll
    for (int i = 0; i < 32; i += 8)
        t[y + i][x] = in[(long long)(r0 + y + i) * ldi + c0 + x];
    __syncthreads();
#pragma unroll
    for (int i = 0; i < 32; i += 8)
        out[(long long)(c0 + y + i) * ldo + r0 + x] = __float2half_rn(t[x][y + i]);
}

// LayerNorm rows of 1024: fp32 in -> fp16 out
__global__ __launch_bounds__(256)
void layernorm_h_k(const float* __restrict__ x, __half* __restrict__ xh,
                   const float* __restrict__ g, const float* __restrict__ bt)
{
    __shared__ float sh[8];
    __shared__ float stat[2];
    const float* row = x + (long long)blockIdx.x * 1024;
    __half2* ro = (__half2*)(xh + (long long)blockIdx.x * 1024);
    const int tid  = threadIdx.x;
    const int lane = tid & 31;
    const int wid  = tid >> 5;

    float4 v = ((const float4*)row)[tid];

    float s = v.x + v.y + v.z + v.w;
#pragma unroll
    for (int o = 16; o > 0; o >>= 1) s += __shfl_xor_sync(0xffffffffu, s, o);
    if (lane == 0) sh[wid] = s;
    __syncthreads();
    if (wid == 0) {
        float t = (lane < 8) ? sh[lane] : 0.f;
#pragma unroll
        for (int o = 4; o > 0; o >>= 1) t += __shfl_xor_sync(0xffffffffu, t, o);
        if (lane == 0) stat[0] = t;
    }
    __syncthreads();
    const float mean = stat[0] * (1.f / 1024.f);

    const float dx = v.x - mean, dy = v.y - mean, dz = v.z - mean, dw = v.w - mean;
    float ss = dx * dx + dy * dy + dz * dz + dw * dw;
#pragma unroll
    for (int o = 16; o > 0; o >>= 1) ss += __shfl_xor_sync(0xffffffffu, ss, o);
    __syncthreads();
    if (lane == 0) sh[wid] = ss;
    __syncthreads();
    if (wid == 0) {
        float t = (lane < 8) ? sh[lane] : 0.f;
#pragma unroll
        for (int o = 4; o > 0; o >>= 1) t += __shfl_xor_sync(0xffffffffu, t, o);
        if (lane == 0) stat[1] = t;
    }
    __syncthreads();
    const float inv = rsqrtf(stat[1] * (1.f / 1024.f) + 1e-5f);

    const float4 gg = ((const float4*)g)[tid];
    const float4 bb = ((const float4*)bt)[tid];
    ro[tid * 2]     = __floats2half2_rn(dx * inv * gg.x + bb.x, dy * inv * gg.y + bb.y);
    ro[tid * 2 + 1] = __floats2half2_rn(dz * inv * gg.z + bb.z, dw * inv * gg.w + bb.w);
}

__global__ __launch_bounds__(256)
void inv_k(const float* __restrict__ part, float* __restrict__ inv, int n)
{
    int i = blockIdx.x * 256 + threadIdx.x;
    if (i < n) {
        const float4* p = (const float4*)(part + ((long long)i << 4));
        float4 a = p[0], b = p[1], c = p[2], d = p[3];
        float s = ((a.x + a.y) + (a.z + a.w)) + ((b.x + b.y) + (b.z + b.w))
                + ((c.x + c.y) + (c.z + c.w)) + ((d.x + d.y) + (d.z + d.w));
        inv[i] = 1.f / s;
    }
}

__global__ __launch_bounds__(256)
void bcat_k(const float* __restrict__ b0, const float* __restrict__ b1,
            float* __restrict__ out)
{
    int i = blockIdx.x * 256 + threadIdx.x;
    if (i < 2048) out[i] = (i < 1024) ? b0[i] : b1[i - 1024];
}

// v' = fp16(v * inv[n])
__global__ __launch_bounds__(256)
void vscale_h_k(const float4* __restrict__ v, const float* __restrict__ inv,
                __half2* __restrict__ out)
{
    const long long i = (long long)blockIdx.x * 256 + threadIdx.x;
    const int b  = (int)(i >> 16);          // 65536 float4 per batch
    const int n4 = (int)(i & 255);
    float4 vv = v[i];
    const float4 iv = *(const float4*)(inv + (long long)b * 2048 + n4 * 4);
    out[2 * i]     = __floats2half2_rn(vv.x * iv.x, vv.y * iv.y);
    out[2 * i + 1] = __floats2half2_rn(vv.z * iv.z, vv.w * iv.w);
}

// ---------------- launcher ----------------
extern "C" void kernel_launch(void* const* d_in, const int* in_sizes, int n_in,
                              void* d_out, int out_size)
{
    const float* x_spa  = (const float*)d_in[0];
    const float* x_freq = (const float*)d_in[1];
    const float* w_cdc  = (const float*)d_in[2];
    const float* b_cdc  = (const float*)d_in[3];
    const float* w_sv   = (const float*)d_in[4];
    const float* b_sv   = (const float*)d_in[5];
    const float* w_fv   = (const float*)d_in[6];
    const float* b_fv   = (const float*)d_in[7];
    const float* ln_w   = (const float*)d_in[8];
    const float* ln_b   = (const float*)d_in[9];
    const float* w_qk   = (const float*)d_in[10];
    const float* w_spa  = (const float*)d_in[11];
    const float* b_spa  = (const float*)d_in[12];
    const float* w_frq  = (const float*)d_in[13];
    const float* b_frq  = (const float*)d_in[14];

    float* out_spa  = (float*)d_out;
    float* out_freq = (float*)d_out + (long long)NB * NC * HW;

    float *p_x, *p_vspa, *p_vfreq, *p_part, *p_inv, *p_bcat;
    __half *p_xTcat, *p_wcdc, *p_wsv, *p_wfv, *p_wqk, *p_wcat;
    __half *p_xh, *p_qkh, *p_qTh, *p_kwTh, *p_ET, *p_vs1, *p_vs2;
    cudaGetSymbolAddress((void**)&p_x,     g_x);
    cudaGetSymbolAddress((void**)&p_vspa,  g_vspa);
    cudaGetSymbolAddress((void**)&p_vfreq, g_vfreq);
    cudaGetSymbolAddress((void**)&p_part,  g_part);
    cudaGetSymbolAddress((void**)&p_inv,   g_inv);
    cudaGetSymbolAddress((void**)&p_bcat,  g_bcat);
    cudaGetSymbolAddress((void**)&p_xTcat, g_xTcat_h);
    cudaGetSymbolAddress((void**)&p_wcdc,  g_wcdc_h);
    cudaGetSymbolAddress((void**)&p_wsv,   g_wsv_h);
    cudaGetSymbolAddress((void**)&p_wfv,   g_wfv_h);
    cudaGetSymbolAddress((void**)&p_wqk,   g_wqk_h);
    cudaGetSymbolAddress((void**)&p_wcat,  g_wcat_h);
    cudaGetSymbolAddress((void**)&p_xh,    g_xh);
    cudaGetSymbolAddress((void**)&p_qkh,   g_qk_h);
    cudaGetSymbolAddress((void**)&p_qTh,   g_qT_h);
    cudaGetSymbolAddress((void**)&p_kwTh,  g_kwT_h);
    cudaGetSymbolAddress((void**)&p_ET,    g_ET_h);
    cudaGetSymbolAddress((void**)&p_vs1,   g_vs1_h);
    cudaGetSymbolAddress((void**)&p_vs2,   g_vs2_h);

    static int smem_set = 0;
    if (!smem_set) {
        cudaFuncSetAttribute(gemm_h, cudaFuncAttributeMaxDynamicSharedMemorySize, SMEMH_BYTES);
        smem_set = 1;
    }

    const long long sX   = (long long)NC * HW;      // 262144
    const long long sXT  = (long long)HW * 512;
    const long long sQKh = (long long)NC * 2 * HW;
    const long long sQTh = (long long)HW * NC;
    const long long sKWT = (long long)2 * HW * NC;
    const long long sET  = (long long)2 * HW * HW;  // 2097152 halves
    const dim3 tb(32, 8);
    const float scale = 0.03125f;

    // xTcat = [x_spa^T | x_freq^T] fp16
    transpose_h_k<<<dim3(HW / 32, NC / 32, NB), tb>>>(x_spa, 1024, sX, p_xTcat, 512, sXT);
    transpose_h_k<<<dim3(HW / 32, NC / 32, NB), tb>>>(x_freq, 1024, sX, p_xTcat + 256, 512, sXT);

    // weight rounds -> fp16
    round_h_k<<<(NC * 2 * NC / 4 + 255) / 256, 256>>>((const float4*)w_cdc, (__half2*)p_wcdc, NC * 2 * NC / 4);
    round_h_k<<<(NC * NC / 4 + 255) / 256, 256>>>((const float4*)w_sv, (__half2*)p_wsv, NC * NC / 4);
    round_h_k<<<(NC * NC / 4 + 255) / 256, 256>>>((const float4*)w_fv, (__half2*)p_wfv, NC * NC / 4);

    // cdc: X = w_cdc @ [x_spa; x_freq] + b_cdc   (fp32 out for LN)
    gemm_h<<<dim3(HW / BNH, NC / BMH, NB), 128, SMEMH_BYTES>>>(
        p_wcdc, 512, 0, p_xTcat, 512, sXT, b_cdc, nullptr, nullptr, 0,
        p_x, 1024, sX, 512, 1.f, 0, nullptr, nullptr);

    // v_spa / v_freq (fp32 out; vscale converts later)
    gemm_h<<<dim3(HW / BNH, NC / BMH, NB), 128, SMEMH_BYTES>>>(
        p_wsv, 256, 0, p_xTcat, 512, sXT, b_sv, nullptr, nullptr, 0,
        p_vspa, 1024, sX, 256, 1.f, 0, nullptr, nullptr);
    gemm_h<<<dim3(HW / BNH, NC / BMH, NB), 128, SMEMH_BYTES>>>(
        p_wfv, 256, 0, p_xTcat + 256, 512, sXT, b_fv, nullptr, nullptr, 0,
        p_vfreq, 1024, sX, 256, 1.f, 0, nullptr, nullptr);

    // more weight rounds + bias concat
    round_h_k<<<(2 * DIM * DIM / 4 + 255) / 256, 256>>>((const float4*)w_qk, (__half2*)p_wqk, 2 * DIM * DIM / 4);
    round_h_k<<<(DIM * DIM / 4 + 255) / 256, 256>>>((const float4*)w_spa, (__half2*)p_wcat, DIM * DIM / 4);
    round_h_k<<<(DIM * DIM / 4 + 255) / 256, 256>>>((const float4*)w_frq, (__half2*)(p_wcat + DIM * DIM), DIM * DIM / 4);
    bcat_k<<<8, 256>>>(b_spa, b_frq, p_bcat);

    // LN: fp32 X -> fp16 Xh
    layernorm_h_k<<<NB * NC, 256>>>(p_x, p_xh, ln_w, ln_b);

    // qk: q half -> qT_h transposed; k half -> g_qk_h
    gemm_h<<<dim3(2048 / BNH, NC / BMH, NB), 128, SMEMH_BYTES>>>(
        p_xh, 1024, sX, p_wqk, 1024, 0, nullptr, nullptr, nullptr, 0,
        p_qkh, 2048, sQKh, 1024, 1.f, 1, nullptr, p_qTh);

    // kwT = wcat @ k^T
    gemm_h<<<dim3(NC / BNH, 2 * HW / BMH, NB), 128, SMEMH_BYTES>>>(
        p_wcat, 1024, 0, p_qkh + 1024, 2048, sQKh, nullptr, nullptr, nullptr, 0,
        p_kwTh, 256, sKWT, 1024, 1.f, 1, nullptr, nullptr);

    // ET = exp(scale * qT @ kwT^T + bcat), stored transposed fp16 + partials
    gemm_h<<<dim3(2048 / BNH, HW / BMH, NB), 128, SMEMH_BYTES>>>(
        p_qTh, 256, sQTh, p_kwTh, 256, sKWT, nullptr, p_bcat, nullptr, 0,
        p_ET, 1024, sET, 256, scale, 3, p_part, nullptr);

    // inverse row sums
    inv_k<<<(NB * 2 * HW + 255) / 256, 256>>>(p_part, p_inv, NB * 2 * HW);

    // v' = fp16(v * inv)
    vscale_h_k<<<NB * NC * HW / 4 / 256, 256>>>((const float4*)p_vspa,  p_inv,        (__half2*)p_vs1);
    vscale_h_k<<<NB * NC * HW / 4 / 256, 256>>>((const float4*)p_vfreq, p_inv + 1024, (__half2*)p_vs2);

    // final fp16 GEMMs: out = x + v' @ ET_branch^T
    gemm_h<<<dim3(HW / BNH, NC / BMH, NB), 128, SMEMH_BYTES>>>(
        p_vs1, 1024, sX, p_ET, 1024, sET, nullptr, nullptr, x_spa, sX,
        out_spa, 1024, sX, 1024, 1.f, 4, nullptr, nullptr);
    gemm_h<<<dim3(HW / BNH, NC / BMH, NB), 128, SMEMH_BYTES>>>(
        p_vs2, 1024, sX, p_ET + (long long)HW * HW, 1024, sET, nullptr, nullptr, x_freq, sX,
        out_freq, 1024, sX, 1024, 1.f, 4, nullptr, nullptr);

    (void)in_sizes; (void)n_in; (void)out_size;
}

// round 17
// speedup vs baseline: 1.4626x; 1.0345x over previous
#include <cuda_runtime.h>
#include <cuda_fp16.h>
#include <cstdint>

// ---------------- problem constants ----------------
#define NB   16
#define NC   256
#define HW   1024
#define DIM  1024

// ---------------- fp32 scratch ----------------
__device__ float g_x[NB * NC * HW];            // cdc output fp32 (LN reads)
__device__ float g_part[NB * 2 * HW * 16];
__device__ float g_inv[NB * 2 * HW];
__device__ float g_bcat[2 * HW];

// ---------------- fp16 scratch ----------------
__device__ __half g_xTcat_h[NB * HW * 512];    // [b][n][512] = xT_spa | xT_freq
__device__ __half g_wcdc_h[NC * 2 * NC];
__device__ __half g_wsv_h[NC * NC];
__device__ __half g_wfv_h[NC * NC];
__device__ __half g_wqk_h[2 * DIM * DIM];      // [2048][1024] = [n][k]
__device__ __half g_wcat_h[2 * DIM * DIM];     // [w_spa; w_frq]
__device__ __half g_xh[NB * NC * HW];          // LN output fp16
__device__ __half g_qk_h[NB * NC * 2 * HW];    // k half at cols 1024..
__device__ __half g_qT_h[NB * HW * NC];        // [b][n][c]
__device__ __half g_kwT_h[NB * 2 * HW * NC];   // [b][o'][c]
__device__ __half g_ET_h[NB * 2 * HW * HW];    // [b][o(2048)][n(1024)] exp transposed
__device__ __half g_vs1_h[NB * NC * HW];       // v_spa fp16 (then v*inv in place)
__device__ __half g_vs2_h[NB * NC * HW];       // v_freq fp16

// ---------------- helpers ----------------
__device__ __forceinline__ void cpasync16(uint32_t dst, const void* src) {
    asm volatile("cp.async.cg.shared.global [%0], [%1], 16;\n" :: "r"(dst), "l"(src));
}
__device__ __forceinline__ void cpcommit() {
    asm volatile("cp.async.commit_group;\n");
}
__device__ __forceinline__ void cpwait1() {
    asm volatile("cp.async.wait_group 1;\n");
}
__device__ __forceinline__ void cpwait0() {
    asm volatile("cp.async.wait_group 0;\n");
}
__device__ __forceinline__ void mma_f16(float* d, const uint32_t* a, const uint32_t* b) {
    asm volatile(
        "mma.sync.aligned.m16n8k16.row.col.f32.f16.f16.f32 "
        "{%0,%1,%2,%3}, {%4,%5,%6,%7}, {%8,%9}, {%0,%1,%2,%3};\n"
        : "+f"(d[0]), "+f"(d[1]), "+f"(d[2]), "+f"(d[3])
        : "r"(a[0]), "r"(a[1]), "r"(a[2]), "r"(a[3]), "r"(b[0]), "r"(b[1]));
}

// =====================================================================
// fp16 tensor-core GEMM: C[m,n] = alpha * sum_k A[m,k]*B[n,k]  (B given [n][k])
// mode 0: C fp32 = acc + biasRow
// mode 1: C fp16 = rn(acc + biasRow)
// mode 3: exp epilogue -> ET fp16 TRANSPOSED ([o][n], ld 1024) + partials
// mode 4: C fp32 = acc + Add (residual)
// qTp != nullptr && bn < 1024: write ONLY transposed fp16 qT[b][n][c]
// Pair mode: if blockIdx.z >= 16, use A2/B2/biasRow2/Add2/Cp2 with bz-16.
// =====================================================================
#define BMH 128
#define BNH 128
#define BKH 32
#define LDH 40                         // halves per smem row (80B)
#define AH_HALVES (BMH * LDH)          // 5120
#define STAGEH_BYTES (2 * AH_HALVES * 2)   // 20480
#define NSTH 3
#define SMEMH_BYTES 66560

__global__ __launch_bounds__(128, 3)
void gemm_h(const __half* __restrict__ A, int lda, long long sA,
            const __half* __restrict__ B, int ldb, long long sB,
            const float* __restrict__ biasRow, const float* __restrict__ biasCol,
            const float* __restrict__ Add, long long sAdd,
            void* __restrict__ Cp, int ldc, long long sC,
            int K, float alpha, int mode,
            float* __restrict__ partials, __half* __restrict__ qTp,
            const __half* A2, const __half* B2,
            const float* biasRow2, const float* Add2, void* Cp2)
{
    extern __shared__ float smem[];
    const uint32_t smem_u32 = (uint32_t)__cvta_generic_to_shared(smem);

    long long bz = blockIdx.z;
    if (bz >= NB) {
        bz -= NB;
        A = A2; B = B2; biasRow = biasRow2; Add = Add2; Cp = Cp2;
    }
    A += bz * sA;
    B += bz * sB;
    if (Add) Add += bz * sAdd;

    const int bm = blockIdx.y * BMH;
    const int bn = blockIdx.x * BNH;
    const int tid  = threadIdx.x;
    const int lane = tid & 31;
    const int wid  = tid >> 5;
    const int wm = wid >> 1;
    const int wn = wid & 1;
    const int rb = wm * 64;
    const int cb = wn * 64;
    const int lr = lane >> 2;
    const int lc = lane & 3;

    float acc[4][8][4];
#pragma unroll
    for (int i = 0; i < 4; i++)
#pragma unroll
        for (int j = 0; j < 8; j++)
#pragma unroll
            for (int v = 0; v < 4; v++) acc[i][j][v] = 0.f;

    const int l_row = tid >> 2;          // 0..31
    const int l_ck  = tid & 3;

    const int T = K / BKH;

    auto load_stage = [&](int t, int s) {
        const int k0 = t * BKH;
        const uint32_t sa = smem_u32 + s * STAGEH_BYTES;
        const uint32_t sb = sa + AH_HALVES * 2;
#pragma unroll
        for (int u = 0; u < 4; u++) {
            const int row = l_row + u * 32;
            cpasync16(sa + row * 80 + l_ck * 16,
                      A + (long long)(bm + row) * lda + k0 + l_ck * 8);
        }
#pragma unroll
        for (int u = 0; u < 4; u++) {
            const int row = l_row + u * 32;
            cpasync16(sb + row * 80 + l_ck * 16,
                      B + (long long)(bn + row) * ldb + k0 + l_ck * 8);
        }
    };

    load_stage(0, 0); cpcommit();
    if (T > 1) { load_stage(1, 1); cpcommit(); }

    for (int t = 0; t < T; t++) {
        if (t < T - 1) cpwait1(); else cpwait0();
        __syncthreads();
        if (t + 2 < T) { load_stage(t + 2, (t + 2) % NSTH); }
        cpcommit();

        const char* sAc = (const char*)smem + (t % NSTH) * STAGEH_BYTES;
        const char* sBc = sAc + AH_HALVES * 2;

#pragma unroll
        for (int kk = 0; kk < 2; kk++) {
            const int kb = kk * 16;
            uint32_t a[4][4];
#pragma unroll
            for (int mi = 0; mi < 4; mi++) {
                const int m0 = rb + mi * 16 + lr;
                a[mi][0] = *(const uint32_t*)(sAc + (m0 * LDH + kb + 2 * lc) * 2);
                a[mi][1] = *(const uint32_t*)(sAc + ((m0 + 8) * LDH + kb + 2 * lc) * 2);
                a[mi][2] = *(const uint32_t*)(sAc + (m0 * LDH + kb + 2 * lc + 8) * 2);
                a[mi][3] = *(const uint32_t*)(sAc + ((m0 + 8) * LDH + kb + 2 * lc + 8) * 2);
            }
            uint32_t b[8][2];
#pragma unroll
            for (int ni = 0; ni < 8; ni++) {
                const int n0 = cb + ni * 8 + lr;
                b[ni][0] = *(const uint32_t*)(sBc + (n0 * LDH + kb + 2 * lc) * 2);
                b[ni][1] = *(const uint32_t*)(sBc + (n0 * LDH + kb + 2 * lc + 8) * 2);
            }
#pragma unroll
            for (int mi = 0; mi < 4; mi++)
#pragma unroll
                for (int ni = 0; ni < 8; ni++)
                    mma_f16(acc[mi][ni], a[mi], b[ni]);
        }
        __syncthreads();
    }

    if (qTp && bn < 1024) {
        // q half: stage fp32 tile, write fp16 transposed qT[b][n][c]
        float* s = smem;
#pragma unroll
        for (int mi = 0; mi < 4; mi++)
#pragma unroll
            for (int hh = 0; hh < 2; hh++) {
                const int rl = rb + mi * 16 + lr + hh * 8;
#pragma unroll
                for (int ni = 0; ni < 8; ni++) {
                    const int cl = cb + ni * 8 + lc * 2;
                    s[rl * 129 + cl]     = acc[mi][ni][hh * 2 + 0];
                    s[rl * 129 + cl + 1] = acc[mi][ni][hh * 2 + 1];
                }
            }
        __syncthreads();
        __half* qTb = qTp + bz * (long long)(HW * NC);
        for (int i = 0; i < 32; i++) {
            const int nl = wid * 32 + i;
            __half* row = qTb + (long long)(bn + nl) * 256 + bm;
#pragma unroll
            for (int u = 0; u < 4; u++)
                row[lane + 32 * u] = __float2half_rn(s[(lane + 32 * u) * 129 + nl]);
        }
        return;
    }

    if (mode == 3) {
        // exp epilogue: partials + TRANSPOSED fp16 store ET[o][n]
        __half* ET = (__half*)Cp + bz * sC;
        const int h = bn >> 10;
        const int slot = ((bn & 1023) + cb) >> 6;
        float* s = smem;
#pragma unroll
        for (int mi = 0; mi < 4; mi++)
#pragma unroll
            for (int hh = 0; hh < 2; hh++) {
                const int rl = rb + mi * 16 + lr + hh * 8;   // local n row
                const int r = bm + rl;                        // global n
                float rowsum = 0.f;
#pragma unroll
                for (int ni = 0; ni < 8; ni++) {
                    const int cl = cb + ni * 8 + lc * 2;      // local o col
                    const float2 bc = *(const float2*)(biasCol + bn + cl);
                    float f0 = alpha * acc[mi][ni][hh * 2 + 0] + bc.x;
                    float f1 = alpha * acc[mi][ni][hh * 2 + 1] + bc.y;
                    f0 = fminf(fmaxf(f0, -15.f), 11.f);
                    f1 = fminf(fmaxf(f1, -15.f), 11.f);
                    const __half h0 = __float2half_rn(__expf(f0));
                    const __half h1 = __float2half_rn(__expf(f1));
                    const float e0 = __half2float(h0);
                    const float e1 = __half2float(h1);
                    rowsum += e0 + e1;
                    s[rl * 129 + cl]     = e0;
                    s[rl * 129 + cl + 1] = e1;
                }
                rowsum += __shfl_xor_sync(0xffffffffu, rowsum, 1);
                rowsum += __shfl_xor_sync(0xffffffffu, rowsum, 2);
                if (lc == 0) {
                    const long long pidx =
                        (((long long)bz * 2048 + h * 1024 + r) << 4) + slot;
                    partials[pidx] = rowsum;
                }
            }
        __syncthreads();
        for (int i = 0; i < 32; i++) {
            const int ol = wid * 32 + i;
            __half2* row = (__half2*)(ET + (long long)(bn + ol) * 1024 + bm);
#pragma unroll
            for (int u = 0; u < 2; u++) {
                const int nl = 2 * lane + 64 * u;
                row[lane + 32 * u] = __floats2half2_rn(s[nl * 129 + ol],
                                                       s[(nl + 1) * 129 + ol]);
            }
        }
        return;
    }

    if (mode == 1) {
        __half* C = (__half*)Cp + bz * sC;
#pragma unroll
        for (int mi = 0; mi < 4; mi++)
#pragma unroll
            for (int hh = 0; hh < 2; hh++) {
                const int r = bm + rb + mi * 16 + lr + hh * 8;
                const float br = biasRow ? biasRow[r] : 0.f;
                const long long rowoff = (long long)r * ldc;
#pragma unroll
                for (int ni = 0; ni < 8; ni++) {
                    const int c = bn + cb + ni * 8 + lc * 2;
                    *(__half2*)(C + rowoff + c) =
                        __floats2half2_rn(alpha * acc[mi][ni][hh * 2 + 0] + br,
                                          alpha * acc[mi][ni][hh * 2 + 1] + br);
                }
            }
    } else if (mode == 4) {
        float* C = (float*)Cp + bz * sC;
#pragma unroll
        for (int mi = 0; mi < 4; mi++)
#pragma unroll
            for (int hh = 0; hh < 2; hh++) {
                const int r = bm + rb + mi * 16 + lr + hh * 8;
                const long long rowoff = (long long)r * ldc;
#pragma unroll
                for (int ni = 0; ni < 8; ni++) {
                    const int c = bn + cb + ni * 8 + lc * 2;
                    const float2 ad = *(const float2*)(Add + rowoff + c);
                    float2 o;
                    o.x = acc[mi][ni][hh * 2 + 0] + ad.x;
                    o.y = acc[mi][ni][hh * 2 + 1] + ad.y;
                    *(float2*)(C + rowoff + c) = o;
                }
            }
    } else {
        float* C = (float*)Cp + bz * sC;
#pragma unroll
        for (int mi = 0; mi < 4; mi++)
#pragma unroll
            for (int hh = 0; hh < 2; hh++) {
                const int r = bm + rb + mi * 16 + lr + hh * 8;
                const float br = biasRow ? biasRow[r] : 0.f;
                const long long rowoff = (long long)r * ldc;
#pragma unroll
                for (int ni = 0; ni < 8; ni++) {
                    const int c = bn + cb + ni * 8 + lc * 2;
                    float2 o;
                    o.x = acc[mi][ni][hh * 2 + 0] + br;
                    o.y = acc[mi][ni][hh * 2 + 1] + br;
                    *(float2*)(C + rowoff + c) = o;
                }
            }
    }
}

// ---------------- elementwise kernels ----------------
__global__ __launch_bounds__(256)
void round_h_k(const float4* __restrict__ in, __half2* __restrict__ out, int n4)
{
    int i = blockIdx.x * 256 + threadIdx.x;
    if (i < n4) {
        float4 v = in[i];
        out[2 * i]     = __floats2half2_rn(v.x, v.y);
        out[2 * i + 1] = __floats2half2_rn(v.z, v.w);
    }
}

// paired transpose fp32 -> fp16: z >= 16 selects (in2, out2)
__global__ __launch_bounds__(256)
void transpose_h2_k(const float* __restrict__ in, const float* __restrict__ in2,
                    __half* __restrict__ out, __half* __restrict__ out2,
                    int ldi, long long sIn, int ldo, long long sOut)
{
    __shared__ float t[32][33];
    long long z = blockIdx.z;
    if (z >= NB) { z -= NB; in = in2; out = out2; }
    in  += z * sIn;
    out += z * sOut;
    const int r0 = blockIdx.y * 32;
    const int c0 = blockIdx.x * 32;
    const int x = threadIdx.x;
    const int y = threadIdx.y;
#pragma unroll
    for (int i = 0; i < 32; i += 8)
        t[y + i][x] = in[(long long)(r0 + y + i) * ldi + c0 + x];
    __syncthreads();
#pragma unroll
    for (int i = 0; i < 32; i += 8)
        out[(long long)(c0 + y + i) * ldo + r0 + x] = __float2half_rn(t[x][y + i]);
}

// LayerNorm rows of 1024: fp32 in -> fp16 out
__global__ __launch_bounds__(256)
void layernorm_h_k(const float* __restrict__ x, __half* __restrict__ xh,
                   const float* __restrict__ g, const float* __restrict__ bt)
{
    __shared__ float sh[8];
    __shared__ float stat[2];
    const float* row = x + (long long)blockIdx.x * 1024;
    __half2* ro = (__half2*)(xh + (long long)blockIdx.x * 1024);
    const int tid  = threadIdx.x;
    const int lane = tid & 31;
    const int wid  = tid >> 5;

    float4 v = ((const float4*)row)[tid];

    float s = v.x + v.y + v.z + v.w;
#pragma unroll
    for (int o = 16; o > 0; o >>= 1) s += __shfl_xor_sync(0xffffffffu, s, o);
    if (lane == 0) sh[wid] = s;
    __syncthreads();
    if (wid == 0) {
        float t = (lane < 8) ? sh[lane] : 0.f;
#pragma unroll
        for (int o = 4; o > 0; o >>= 1) t += __shfl_xor_sync(0xffffffffu, t, o);
        if (lane == 0) stat[0] = t;
    }
    __syncthreads();
    const float mean = stat[0] * (1.f / 1024.f);

    const float dx = v.x - mean, dy = v.y - mean, dz = v.z - mean, dw = v.w - mean;
    float ss = dx * dx + dy * dy + dz * dz + dw * dw;
#pragma unroll
    for (int o = 16; o > 0; o >>= 1) ss += __shfl_xor_sync(0xffffffffu, ss, o);
    __syncthreads();
    if (lane == 0) sh[wid] = ss;
    __syncthreads();
    if (wid == 0) {
        float t = (lane < 8) ? sh[lane] : 0.f;
#pragma unroll
        for (int o = 4; o > 0; o >>= 1) t += __shfl_xor_sync(0xffffffffu, t, o);
        if (lane == 0) stat[1] = t;
    }
    __syncthreads();
    const float inv = rsqrtf(stat[1] * (1.f / 1024.f) + 1e-5f);

    const float4 gg = ((const float4*)g)[tid];
    const float4 bb = ((const float4*)bt)[tid];
    ro[tid * 2]     = __floats2half2_rn(dx * inv * gg.x + bb.x, dy * inv * gg.y + bb.y);
    ro[tid * 2 + 1] = __floats2half2_rn(dz * inv * gg.z + bb.z, dw * inv * gg.w + bb.w);
}

__global__ __launch_bounds__(256)
void inv_k(const float* __restrict__ part, float* __restrict__ inv, int n)
{
    int i = blockIdx.x * 256 + threadIdx.x;
    if (i < n) {
        const float4* p = (const float4*)(part + ((long long)i << 4));
        float4 a = p[0], b = p[1], c = p[2], d = p[3];
        float s = ((a.x + a.y) + (a.z + a.w)) + ((b.x + b.y) + (b.z + b.w))
                + ((c.x + c.y) + (c.z + c.w)) + ((d.x + d.y) + (d.z + d.w));
        inv[i] = 1.f / s;
    }
}

__global__ __launch_bounds__(256)
void bcat_k(const float* __restrict__ b0, const float* __restrict__ b1,
            float* __restrict__ out)
{
    int i = blockIdx.x * 256 + threadIdx.x;
    if (i < 2048) out[i] = (i < 1024) ? b0[i] : b1[i - 1024];
}

// in-place fp16 v *= inv[n]; grid.y = branch (0: v1/inv, 1: v2/inv+1024)
// layout [b][c][1024]; 512 half2 per row; NC*HW/2 = 131072 half2 per batch
__global__ __launch_bounds__(256)
void vscale2_k(__half2* __restrict__ v1, __half2* __restrict__ v2,
               const float* __restrict__ inv)
{
    const int branch = blockIdx.y;
    __half2* v = branch ? v2 : v1;
    const float* ivb = inv + branch * 1024;
    const long long i = (long long)blockIdx.x * 256 + threadIdx.x;  // < 2M
    const int b  = (int)(i >> 17);
    const int n2 = (int)(i & 511);
    const float2 iv = *(const float2*)(ivb + (long long)b * 2048 + n2 * 2);
    const __half2 x = v[i];
    v[i] = __floats2half2_rn(__low2float(x) * iv.x, __high2float(x) * iv.y);
}

// ---------------- launcher ----------------
extern "C" void kernel_launch(void* const* d_in, const int* in_sizes, int n_in,
                              void* d_out, int out_size)
{
    const float* x_spa  = (const float*)d_in[0];
    const float* x_freq = (const float*)d_in[1];
    const float* w_cdc  = (const float*)d_in[2];
    const float* b_cdc  = (const float*)d_in[3];
    const float* w_sv   = (const float*)d_in[4];
    const float* b_sv   = (const float*)d_in[5];
    const float* w_fv   = (const float*)d_in[6];
    const float* b_fv   = (const float*)d_in[7];
    const float* ln_w   = (const float*)d_in[8];
    const float* ln_b   = (const float*)d_in[9];
    const float* w_qk   = (const float*)d_in[10];
    const float* w_spa  = (const float*)d_in[11];
    const float* b_spa  = (const float*)d_in[12];
    const float* w_frq  = (const float*)d_in[13];
    const float* b_frq  = (const float*)d_in[14];

    float* out_spa  = (float*)d_out;
    float* out_freq = (float*)d_out + (long long)NB * NC * HW;

    float *p_x, *p_part, *p_inv, *p_bcat;
    __half *p_xTcat, *p_wcdc, *p_wsv, *p_wfv, *p_wqk, *p_wcat;
    __half *p_xh, *p_qkh, *p_qTh, *p_kwTh, *p_ET, *p_vs1, *p_vs2;
    cudaGetSymbolAddress((void**)&p_x,     g_x);
    cudaGetSymbolAddress((void**)&p_part,  g_part);
    cudaGetSymbolAddress((void**)&p_inv,   g_inv);
    cudaGetSymbolAddress((void**)&p_bcat,  g_bcat);
    cudaGetSymbolAddress((void**)&p_xTcat, g_xTcat_h);
    cudaGetSymbolAddress((void**)&p_wcdc,  g_wcdc_h);
    cudaGetSymbolAddress((void**)&p_wsv,   g_wsv_h);
    cudaGetSymbolAddress((void**)&p_wfv,   g_wfv_h);
    cudaGetSymbolAddress((void**)&p_wqk,   g_wqk_h);
    cudaGetSymbolAddress((void**)&p_wcat,  g_wcat_h);
    cudaGetSymbolAddress((void**)&p_xh,    g_xh);
    cudaGetSymbolAddress((void**)&p_qkh,   g_qk_h);
    cudaGetSymbolAddress((void**)&p_qTh,   g_qT_h);
    cudaGetSymbolAddress((void**)&p_kwTh,  g_kwT_h);
    cudaGetSymbolAddress((void**)&p_ET,    g_ET_h);
    cudaGetSymbolAddress((void**)&p_vs1,   g_vs1_h);
    cudaGetSymbolAddress((void**)&p_vs2,   g_vs2_h);

    static int smem_set = 0;
    if (!smem_set) {
        cudaFuncSetAttribute(gemm_h, cudaFuncAttributeMaxDynamicSharedMemorySize, SMEMH_BYTES);
        smem_set = 1;
    }

    const long long sX   = (long long)NC * HW;      // 262144
    const long long sXT  = (long long)HW * 512;
    const long long sQKh = (long long)NC * 2 * HW;
    const long long sQTh = (long long)HW * NC;
    const long long sKWT = (long long)2 * HW * NC;
    const long long sET  = (long long)2 * HW * HW;
    const dim3 tb(32, 8);
    const float scale = 0.03125f;

    // merged x transposes: z<16 -> x_spa->xTcat[:,:256]^T slot, z>=16 -> x_freq
    transpose_h2_k<<<dim3(HW / 32, NC / 32, 2 * NB), tb>>>(
        x_spa, x_freq, p_xTcat, p_xTcat + 256, 1024, sX, 512, sXT);

    // weight rounds -> fp16
    round_h_k<<<(NC * 2 * NC / 4 + 255) / 256, 256>>>((const float4*)w_cdc, (__half2*)p_wcdc, NC * 2 * NC / 4);
    round_h_k<<<(NC * NC / 4 + 255) / 256, 256>>>((const float4*)w_sv, (__half2*)p_wsv, NC * NC / 4);
    round_h_k<<<(NC * NC / 4 + 255) / 256, 256>>>((const float4*)w_fv, (__half2*)p_wfv, NC * NC / 4);

    // cdc: X = w_cdc @ [x_spa; x_freq] + b_cdc   (fp32 out for LN)
    gemm_h<<<dim3(HW / BNH, NC / BMH, NB), 128, SMEMH_BYTES>>>(
        p_wcdc, 512, 0, p_xTcat, 512, sXT, b_cdc, nullptr, nullptr, 0,
        p_x, 1024, sX, 512, 1.f, 0, nullptr, nullptr,
        nullptr, nullptr, nullptr, nullptr, nullptr);

    // merged v GEMMs (mode 1 fp16 + bias): z<16 spa, z>=16 freq
    gemm_h<<<dim3(HW / BNH, NC / BMH, 2 * NB), 128, SMEMH_BYTES>>>(
        p_wsv, 256, 0, p_xTcat, 512, sXT, b_sv, nullptr, nullptr, 0,
        p_vs1, 1024, sX, 256, 1.f, 1, nullptr, nullptr,
        p_wfv, p_xTcat + 256, b_fv, nullptr, p_vs2);

    // more weight rounds + bias concat
    round_h_k<<<(2 * DIM * DIM / 4 + 255) / 256, 256>>>((const float4*)w_qk, (__half2*)p_wqk, 2 * DIM * DIM / 4);
    round_h_k<<<(DIM * DIM / 4 + 255) / 256, 256>>>((const float4*)w_spa, (__half2*)p_wcat, DIM * DIM / 4);
    round_h_k<<<(DIM * DIM / 4 + 255) / 256, 256>>>((const float4*)w_frq, (__half2*)(p_wcat + DIM * DIM), DIM * DIM / 4);
    bcat_k<<<8, 256>>>(b_spa, b_frq, p_bcat);

    // LN: fp32 X -> fp16 Xh
    layernorm_h_k<<<NB * NC, 256>>>(p_x, p_xh, ln_w, ln_b);

    // qk: q half -> qT_h transposed; k half -> g_qk_h
    gemm_h<<<dim3(2048 / BNH, NC / BMH, NB), 128, SMEMH_BYTES>>>(
        p_xh, 1024, sX, p_wqk, 1024, 0, nullptr, nullptr, nullptr, 0,
        p_qkh, 2048, sQKh, 1024, 1.f, 1, nullptr, p_qTh,
        nullptr, nullptr, nullptr, nullptr, nullptr);

    // kwT = wcat @ k^T
    gemm_h<<<dim3(NC / BNH, 2 * HW / BMH, NB), 128, SMEMH_BYTES>>>(
        p_wcat, 1024, 0, p_qkh + 1024, 2048, sQKh, nullptr, nullptr, nullptr, 0,
        p_kwTh, 256, sKWT, 1024, 1.f, 1, nullptr, nullptr,
        nullptr, nullptr, nullptr, nullptr, nullptr);

    // ET = exp(scale * qT @ kwT^T + bcat), transposed fp16 + partials
    gemm_h<<<dim3(2048 / BNH, HW / BMH, NB), 128, SMEMH_BYTES>>>(
        p_qTh, 256, sQTh, p_kwTh, 256, sKWT, nullptr, p_bcat, nullptr, 0,
        p_ET, 1024, sET, 256, scale, 3, p_part, nullptr,
        nullptr, nullptr, nullptr, nullptr, nullptr);

    // inverse row sums
    inv_k<<<(NB * 2 * HW + 255) / 256, 256>>>(p_part, p_inv, NB * 2 * HW);

    // merged in-place vscale (fp16)
    vscale2_k<<<dim3(NB * NC * HW / 2 / 256, 2), 256>>>(
        (__half2*)p_vs1, (__half2*)p_vs2, p_inv);

    // merged final GEMMs (mode 4): z<16 spa, z>=16 freq
    gemm_h<<<dim3(HW / BNH, NC / BMH, 2 * NB), 128, SMEMH_BYTES>>>(
        p_vs1, 1024, sX, p_ET, 1024, sET, nullptr, nullptr, x_spa, sX,
        out_spa, 1024, sX, 1024, 1.f, 4, nullptr, nullptr,
        p_vs2, p_ET + (long long)HW * HW, nullptr, x_freq, out_freq);

    (void)in_sizes; (void)n_in; (void)out_size;
}